// round 3
// baseline (speedup 1.0000x reference)
#include <cuda_runtime.h>
#include <cstdint>

#define N_NODES 50000
#define N_EDGES 800000
#define D 64
#define N_GRAPHS 512
#define N_LAYERS 3
#define HID_FC 64
#define N_CLASSES 10

// Scratch (device globals: no allocations allowed)
__device__ float g_h[N_NODES * D];
__device__ float g_agg[N_NODES * D];
__device__ unsigned int g_pool[N_GRAPHS * D];
__device__ int g_deg[N_NODES];
__device__ int g_off[N_NODES + 1];
__device__ int g_cur[N_NODES];
__device__ int g_adj[N_EDGES];

// ---------------------------------------------------------------------------
// CSR build: histogram of in-degrees
// ---------------------------------------------------------------------------
__global__ void hist_kernel(const int* __restrict__ dst) {
    int e = blockIdx.x * blockDim.x + threadIdx.x;
    if (e < N_EDGES) atomicAdd(&g_deg[dst[e]], 1);
}

// ---------------------------------------------------------------------------
// CSR build: single-block exclusive scan (1024 threads, ~49 elems each)
// ---------------------------------------------------------------------------
__global__ __launch_bounds__(1024) void scan_kernel() {
    __shared__ int partial[1024];
    int t = threadIdx.x;
    const int CHUNK = (N_NODES + 1023) / 1024;  // 49
    int begin = t * CHUNK;
    int end = begin + CHUNK;
    if (end > N_NODES) end = N_NODES;
    if (begin > N_NODES) begin = N_NODES;

    int s = 0;
    for (int i = begin; i < end; i++) s += g_deg[i];
    partial[t] = s;
    __syncthreads();

    // Hillis-Steele inclusive scan
    for (int d = 1; d < 1024; d <<= 1) {
        int v = (t >= d) ? partial[t - d] : 0;
        __syncthreads();
        partial[t] += v;
        __syncthreads();
    }

    int run = (t > 0) ? partial[t - 1] : 0;
    for (int i = begin; i < end; i++) {
        int dg = g_deg[i];
        g_off[i] = run;
        g_cur[i] = run;
        run += dg;
    }
    if (t == 1023) g_off[N_NODES] = run;  // == N_EDGES
}

// ---------------------------------------------------------------------------
// CSR build: fill adjacency (src ids grouped by dst)
// ---------------------------------------------------------------------------
__global__ void fill_kernel(const int* __restrict__ src, const int* __restrict__ dst) {
    int e = blockIdx.x * blockDim.x + threadIdx.x;
    if (e < N_EDGES) {
        int d = dst[e];
        int pos = atomicAdd(&g_cur[d], 1);
        g_adj[pos] = src[e];
    }
}

// ---------------------------------------------------------------------------
// Gather aggregation: agg[n] = h[n] + sum_{j in N(n)} h[j]
// 16 threads per node, float4 per lane, no atomics.
// ---------------------------------------------------------------------------
__global__ __launch_bounds__(256) void gather_kernel(const float4* __restrict__ hin4,
                                                     float4* __restrict__ agg4) {
    unsigned int gid = blockIdx.x * 256u + threadIdx.x;
    unsigned int node = gid >> 4;
    unsigned int lane = gid & 15u;
    if (node >= N_NODES) return;

    float4 acc = hin4[(size_t)node * 16 + lane];  // self term (eps = 0)
    float4 acc2 = make_float4(0.f, 0.f, 0.f, 0.f);

    int s = g_off[node];
    int e = g_off[node + 1];
    int i = s;
    for (; i + 1 < e; i += 2) {
        int nb0 = __ldg(&g_adj[i]);
        int nb1 = __ldg(&g_adj[i + 1]);
        float4 v0 = hin4[(size_t)nb0 * 16 + lane];
        float4 v1 = hin4[(size_t)nb1 * 16 + lane];
        acc.x += v0.x; acc.y += v0.y; acc.z += v0.z; acc.w += v0.w;
        acc2.x += v1.x; acc2.y += v1.y; acc2.z += v1.z; acc2.w += v1.w;
    }
    if (i < e) {
        int nb = __ldg(&g_adj[i]);
        float4 v = hin4[(size_t)nb * 16 + lane];
        acc.x += v.x; acc.y += v.y; acc.z += v.z; acc.w += v.w;
    }
    acc.x += acc2.x; acc.y += acc2.y; acc.z += acc2.z; acc.w += acc2.w;

    agg4[(size_t)node * 16 + lane] = acc;
}

// ---------------------------------------------------------------------------
// h_out = relu(agg @ W1 + b1) @ W2 + b2
// mode 0: write hout; mode 1: last layer — fused global-max-pool
// ---------------------------------------------------------------------------
__global__ __launch_bounds__(128) void mlp_kernel(const float* __restrict__ xin,
                                                  const float* __restrict__ W1,
                                                  const float* __restrict__ b1,
                                                  const float* __restrict__ W2,
                                                  const float* __restrict__ b2,
                                                  float* __restrict__ hout,
                                                  const int* __restrict__ batch,
                                                  int mode) {
    __shared__ float W1s[D * D];
    __shared__ float W2s[D * D];
    __shared__ float b1s[D];
    __shared__ float b2s[D];

    int tid = threadIdx.x;
    for (int i = tid; i < D * D; i += 128) {
        W1s[i] = W1[i];
        W2s[i] = W2[i];
    }
    if (tid < D) {
        b1s[tid] = b1[tid];
        b2s[tid] = b2[tid];
    }
    __syncthreads();

    int row = blockIdx.x * 128 + tid;
    if (row >= N_NODES) return;

    // ---- GEMM 1: t = relu(x @ W1 + b1) ----
    float t[D];
#pragma unroll
    for (int j = 0; j < D; j++) t[j] = b1s[j];

    {
        const float4* x4 = reinterpret_cast<const float4*>(xin + (size_t)row * D);
#pragma unroll
        for (int k4 = 0; k4 < D / 4; k4++) {
            float4 xv = x4[k4];
            float xk[4] = {xv.x, xv.y, xv.z, xv.w};
#pragma unroll
            for (int kk = 0; kk < 4; kk++) {
                float xs = xk[kk];
                const float4* wrow = reinterpret_cast<const float4*>(W1s + (k4 * 4 + kk) * D);
#pragma unroll
                for (int j4 = 0; j4 < D / 4; j4++) {
                    float4 w = wrow[j4];
                    t[j4 * 4 + 0] += xs * w.x;
                    t[j4 * 4 + 1] += xs * w.y;
                    t[j4 * 4 + 2] += xs * w.z;
                    t[j4 * 4 + 3] += xs * w.w;
                }
            }
        }
    }
#pragma unroll
    for (int j = 0; j < D; j++) t[j] = fmaxf(t[j], 0.0f);

    // ---- GEMM 2: o = t @ W2 + b2, in 4 chunks of 16 outputs ----
    int g = (mode == 1) ? batch[row] : 0;
    unsigned int* poolrow = g_pool + (size_t)g * D;
    float4* o4 = reinterpret_cast<float4*>(hout + (size_t)row * D);

#pragma unroll
    for (int c = 0; c < 4; c++) {
        float o[16];
#pragma unroll
        for (int j = 0; j < 16; j++) o[j] = b2s[c * 16 + j];
#pragma unroll
        for (int k = 0; k < D; k++) {
            float tv = t[k];
            const float4* wrow = reinterpret_cast<const float4*>(W2s + k * D + c * 16);
#pragma unroll
            for (int j4 = 0; j4 < 4; j4++) {
                float4 w = wrow[j4];
                o[j4 * 4 + 0] += tv * w.x;
                o[j4 * 4 + 1] += tv * w.y;
                o[j4 * 4 + 2] += tv * w.z;
                o[j4 * 4 + 3] += tv * w.w;
            }
        }
        if (mode == 0) {
#pragma unroll
            for (int j4 = 0; j4 < 4; j4++)
                o4[c * 4 + j4] = make_float4(o[j4 * 4 + 0], o[j4 * 4 + 1],
                                             o[j4 * 4 + 2], o[j4 * 4 + 3]);
        } else {
#pragma unroll
            for (int j = 0; j < 16; j++) {
                unsigned int bits = __float_as_uint(o[j]);
                unsigned int enc = (bits & 0x80000000u) ? ~bits : (bits | 0x80000000u);
                atomicMax(&poolrow[c * 16 + j], enc);
            }
        }
    }
}

// ---------------------------------------------------------------------------
__global__ void pool_init_kernel() {
    int i = blockIdx.x * blockDim.x + threadIdx.x;
    if (i < N_GRAPHS * D) g_pool[i] = 0x00800000u;  // encode(-FLT_MAX)
}

// ---------------------------------------------------------------------------
// FC head + log_softmax. One block (64 threads) per graph.
// ---------------------------------------------------------------------------
__global__ __launch_bounds__(64) void fc_kernel(const float* __restrict__ fcW1,
                                                const float* __restrict__ fcb1,
                                                const float* __restrict__ fcW2,
                                                const float* __restrict__ fcb2,
                                                float* __restrict__ out) {
    __shared__ float xr[D];
    __shared__ float hid[HID_FC];
    __shared__ float logits[N_CLASSES];
    __shared__ float m_s, lse_s;

    int g = blockIdx.x;
    int t = threadIdx.x;

    unsigned int e = g_pool[(size_t)g * D + t];
    unsigned int u = (e & 0x80000000u) ? (e & 0x7FFFFFFFu) : ~e;
    xr[t] = __uint_as_float(u);
    __syncthreads();

    float a = fcb1[t];
#pragma unroll
    for (int k = 0; k < D; k++) a += xr[k] * fcW1[k * HID_FC + t];
    hid[t] = fmaxf(a, 0.0f);
    __syncthreads();

    if (t < N_CLASSES) {
        float a2 = fcb2[t];
#pragma unroll
        for (int k = 0; k < HID_FC; k++) a2 += hid[k] * fcW2[k * N_CLASSES + t];
        logits[t] = a2;
    }
    __syncthreads();

    if (t == 0) {
        float m = logits[0];
#pragma unroll
        for (int j = 1; j < N_CLASSES; j++) m = fmaxf(m, logits[j]);
        float s = 0.0f;
#pragma unroll
        for (int j = 0; j < N_CLASSES; j++) s += expf(logits[j] - m);
        m_s = m;
        lse_s = logf(s);
    }
    __syncthreads();

    if (t < N_CLASSES) out[(size_t)g * N_CLASSES + t] = logits[t] - m_s - lse_s;
}

// ---------------------------------------------------------------------------
extern "C" void kernel_launch(void* const* d_in, const int* in_sizes, int n_in,
                              void* d_out, int out_size) {
    const float* x      = (const float*)d_in[0];
    const float* convW1 = (const float*)d_in[1];
    const float* convb1 = (const float*)d_in[2];
    const float* convW2 = (const float*)d_in[3];
    const float* convb2 = (const float*)d_in[4];
    const float* fcW1   = (const float*)d_in[5];
    const float* fcb1   = (const float*)d_in[6];
    const float* fcW2   = (const float*)d_in[7];
    const float* fcb2   = (const float*)d_in[8];
    const int* edge_index = (const int*)d_in[9];
    const int* batch      = (const int*)d_in[10];
    float* out = (float*)d_out;

    const int* src = edge_index;
    const int* dst = edge_index + N_EDGES;

    float* h_ptr = nullptr;
    float* agg_ptr = nullptr;
    int* deg_ptr = nullptr;
    cudaGetSymbolAddress((void**)&h_ptr, g_h);
    cudaGetSymbolAddress((void**)&agg_ptr, g_agg);
    cudaGetSymbolAddress((void**)&deg_ptr, g_deg);

    const int edge_blocks = (N_EDGES + 255) / 256;        // 3125
    const int gather_blocks = (N_NODES * 16 + 255) / 256; // 3125
    const int mlp_blocks = (N_NODES + 127) / 128;         // 391

    // ---- CSR build (per replay; deterministic up to fp-add order) ----
    cudaMemsetAsync(deg_ptr, 0, (size_t)N_NODES * sizeof(int));
    pool_init_kernel<<<(N_GRAPHS * D + 255) / 256, 256>>>();
    hist_kernel<<<edge_blocks, 256>>>(dst);
    scan_kernel<<<1, 1024>>>();
    fill_kernel<<<edge_blocks, 256>>>(src, dst);

    // ---- 3 GIN layers ----
    for (int l = 0; l < N_LAYERS; l++) {
        const float* hin = (l == 0) ? x : h_ptr;
        int mode = (l == N_LAYERS - 1) ? 1 : 0;
        gather_kernel<<<gather_blocks, 256>>>((const float4*)hin, (float4*)agg_ptr);
        mlp_kernel<<<mlp_blocks, 128>>>(agg_ptr,
                                        convW1 + (size_t)l * D * D, convb1 + (size_t)l * D,
                                        convW2 + (size_t)l * D * D, convb2 + (size_t)l * D,
                                        h_ptr, batch, mode);
    }

    fc_kernel<<<N_GRAPHS, 64>>>(fcW1, fcb1, fcW2, fcb2, out);
}

// round 4
// speedup vs baseline: 1.3535x; 1.3535x over previous
#include <cuda_runtime.h>
#include <cstdint>

#define N_NODES 50000
#define N_EDGES 800000
#define D 64
#define N_GRAPHS 512
#define N_LAYERS 3
#define HID_FC 64
#define N_CLASSES 10
#define PAD 68   // smem row stride (floats): conflict-free mma fragment access

// Scratch (device globals: no allocations allowed)
__device__ float g_h[N_NODES * D];
__device__ float g_agg[N_NODES * D];
__device__ unsigned int g_pool[N_GRAPHS * D];
__device__ int g_deg[N_NODES];
__device__ int g_off[N_NODES + 1];
__device__ int g_cur[N_NODES];
__device__ int g_adj[N_EDGES];

// ---------------------------------------------------------------------------
// CSR build: histogram of in-degrees (4 edges/thread for MLP)
// ---------------------------------------------------------------------------
__global__ void hist_kernel(const int* __restrict__ dst) {
    int e = (blockIdx.x * blockDim.x + threadIdx.x) * 4;
    if (e >= N_EDGES) return;  // N_EDGES % 4 == 0
    int4 d = *reinterpret_cast<const int4*>(dst + e);
    atomicAdd(&g_deg[d.x], 1);
    atomicAdd(&g_deg[d.y], 1);
    atomicAdd(&g_deg[d.z], 1);
    atomicAdd(&g_deg[d.w], 1);
}

// ---------------------------------------------------------------------------
// CSR build: single-block exclusive scan
// ---------------------------------------------------------------------------
__global__ __launch_bounds__(1024) void scan_kernel() {
    __shared__ int partial[1024];
    int t = threadIdx.x;
    const int CHUNK = (N_NODES + 1023) / 1024;  // 49
    int begin = t * CHUNK;
    int end = begin + CHUNK;
    if (end > N_NODES) end = N_NODES;
    if (begin > N_NODES) begin = N_NODES;

    int s = 0;
    for (int i = begin; i < end; i++) s += g_deg[i];
    partial[t] = s;
    __syncthreads();

    for (int d = 1; d < 1024; d <<= 1) {
        int v = (t >= d) ? partial[t - d] : 0;
        __syncthreads();
        partial[t] += v;
        __syncthreads();
    }

    int run = (t > 0) ? partial[t - 1] : 0;
    for (int i = begin; i < end; i++) {
        int dg = g_deg[i];
        g_off[i] = run;
        g_cur[i] = run;
        run += dg;
    }
    if (t == 1023) g_off[N_NODES] = run;
}

// ---------------------------------------------------------------------------
// CSR build: fill adjacency (4 edges/thread, independent chains)
// ---------------------------------------------------------------------------
__global__ void fill_kernel(const int* __restrict__ src, const int* __restrict__ dst) {
    int e = (blockIdx.x * blockDim.x + threadIdx.x) * 4;
    if (e >= N_EDGES) return;
    int4 d = *reinterpret_cast<const int4*>(dst + e);
    int4 s = *reinterpret_cast<const int4*>(src + e);
    int p0 = atomicAdd(&g_cur[d.x], 1);
    int p1 = atomicAdd(&g_cur[d.y], 1);
    int p2 = atomicAdd(&g_cur[d.z], 1);
    int p3 = atomicAdd(&g_cur[d.w], 1);
    g_adj[p0] = s.x;
    g_adj[p1] = s.y;
    g_adj[p2] = s.z;
    g_adj[p3] = s.w;
}

// ---------------------------------------------------------------------------
// Gather aggregation: agg[n] = h[n] + sum_{j in N(n)} h[j]
// ---------------------------------------------------------------------------
__global__ __launch_bounds__(256) void gather_kernel(const float4* __restrict__ hin4,
                                                     float4* __restrict__ agg4) {
    unsigned int gid = blockIdx.x * 256u + threadIdx.x;
    unsigned int node = gid >> 4;
    unsigned int lane = gid & 15u;
    if (node >= N_NODES) return;

    float4 acc = hin4[(size_t)node * 16 + lane];  // self term (eps = 0)
    float4 acc2 = make_float4(0.f, 0.f, 0.f, 0.f);

    int s = g_off[node];
    int e = g_off[node + 1];
    int i = s;
    for (; i + 1 < e; i += 2) {
        int nb0 = __ldg(&g_adj[i]);
        int nb1 = __ldg(&g_adj[i + 1]);
        float4 v0 = hin4[(size_t)nb0 * 16 + lane];
        float4 v1 = hin4[(size_t)nb1 * 16 + lane];
        acc.x += v0.x; acc.y += v0.y; acc.z += v0.z; acc.w += v0.w;
        acc2.x += v1.x; acc2.y += v1.y; acc2.z += v1.z; acc2.w += v1.w;
    }
    if (i < e) {
        int nb = __ldg(&g_adj[i]);
        float4 v = hin4[(size_t)nb * 16 + lane];
        acc.x += v.x; acc.y += v.y; acc.z += v.z; acc.w += v.w;
    }
    acc.x += acc2.x; acc.y += acc2.y; acc.z += acc2.z; acc.w += acc2.w;

    agg4[(size_t)node * 16 + lane] = acc;
}

// ---------------------------------------------------------------------------
// TF32 tensor-core fused MLP: h_out = relu(agg @ W1 + b1) @ W2 + b2
// Block = 128 threads (4 warps) = 64-row tile. mma.sync m16n8k8 tf32.
// mode 0: write hout; mode 1: fused global-max-pool into g_pool
// ---------------------------------------------------------------------------
__device__ __forceinline__ uint32_t f2tf(float f) {
    uint32_t u;
    asm("cvt.rna.tf32.f32 %0, %1;" : "=r"(u) : "f"(f));
    return u;
}

__device__ __forceinline__ void mma_tf32(float* c, uint32_t a0, uint32_t a1,
                                         uint32_t a2, uint32_t a3,
                                         uint32_t b0, uint32_t b1) {
    asm volatile(
        "mma.sync.aligned.m16n8k8.row.col.f32.tf32.tf32.f32 "
        "{%0,%1,%2,%3}, {%4,%5,%6,%7}, {%8,%9}, {%0,%1,%2,%3};"
        : "+f"(c[0]), "+f"(c[1]), "+f"(c[2]), "+f"(c[3])
        : "r"(a0), "r"(a1), "r"(a2), "r"(a3), "r"(b0), "r"(b1));
}

__global__ __launch_bounds__(128) void mlp_tc_kernel(const float* __restrict__ xin,
                                                     const float* __restrict__ W1,
                                                     const float* __restrict__ b1,
                                                     const float* __restrict__ W2,
                                                     const float* __restrict__ b2,
                                                     float* __restrict__ hout,
                                                     const int* __restrict__ batch,
                                                     int mode) {
    __shared__ float As[64 * PAD];   // input tile, then T tile (tf32 bits)
    __shared__ float Ws[64 * PAD];   // W1, then W2 (tf32 bits)
    __shared__ float b1s[D];
    __shared__ float b2s[D];

    int tid = threadIdx.x;
    int warp = tid >> 5;
    int lane = tid & 31;
    int g = lane >> 2;   // group 0..7 (row within fragment)
    int th = lane & 3;   // thread-in-group 0..3
    int arow = warp * 16;
    int row0 = blockIdx.x * 64;

    // ---- stage A tile (zero-padded past N_NODES) + W1, tf32-converted ----
    for (int i = tid; i < 64 * 16; i += 128) {
        int r = i >> 4;
        int c4 = (i & 15) << 2;
        float4 v = make_float4(0.f, 0.f, 0.f, 0.f);
        if (row0 + r < N_NODES)
            v = reinterpret_cast<const float4*>(xin)[(size_t)(row0 + r) * 16 + (c4 >> 2)];
        uint4 t;
        t.x = f2tf(v.x); t.y = f2tf(v.y); t.z = f2tf(v.z); t.w = f2tf(v.w);
        *reinterpret_cast<uint4*>(&As[r * PAD + c4]) = t;

        float4 w = reinterpret_cast<const float4*>(W1)[i];
        uint4 tw;
        tw.x = f2tf(w.x); tw.y = f2tf(w.y); tw.z = f2tf(w.z); tw.w = f2tf(w.w);
        *reinterpret_cast<uint4*>(&Ws[r * PAD + c4]) = tw;
    }
    if (tid < D) { b1s[tid] = b1[tid]; b2s[tid] = b2[tid]; }
    __syncthreads();

    // ---- GEMM 1: acc = A @ W1 ----
    float acc[8][4];
#pragma unroll
    for (int n = 0; n < 8; n++)
#pragma unroll
        for (int j = 0; j < 4; j++) acc[n][j] = 0.f;

#pragma unroll
    for (int k = 0; k < 8; k++) {
        uint32_t a0 = __float_as_uint(As[(arow + g) * PAD + k * 8 + th]);
        uint32_t a1 = __float_as_uint(As[(arow + g + 8) * PAD + k * 8 + th]);
        uint32_t a2 = __float_as_uint(As[(arow + g) * PAD + k * 8 + th + 4]);
        uint32_t a3 = __float_as_uint(As[(arow + g + 8) * PAD + k * 8 + th + 4]);
#pragma unroll
        for (int n = 0; n < 8; n++) {
            uint32_t bf0 = __float_as_uint(Ws[(k * 8 + th) * PAD + n * 8 + g]);
            uint32_t bf1 = __float_as_uint(Ws[(k * 8 + th + 4) * PAD + n * 8 + g]);
            mma_tf32(acc[n], a0, a1, a2, a3, bf0, bf1);
        }
    }

    // ---- bias + relu ----
#pragma unroll
    for (int n = 0; n < 8; n++) {
        int c = n * 8 + 2 * th;
        acc[n][0] = fmaxf(acc[n][0] + b1s[c], 0.f);
        acc[n][1] = fmaxf(acc[n][1] + b1s[c + 1], 0.f);
        acc[n][2] = fmaxf(acc[n][2] + b1s[c], 0.f);
        acc[n][3] = fmaxf(acc[n][3] + b1s[c + 1], 0.f);
    }

    __syncthreads();  // all warps done reading As/Ws of GEMM1

    // ---- write T (tf32) into As; stage W2 into Ws ----
#pragma unroll
    for (int n = 0; n < 8; n++) {
        int c = n * 8 + 2 * th;
        uint2 lo = make_uint2(f2tf(acc[n][0]), f2tf(acc[n][1]));
        uint2 hi = make_uint2(f2tf(acc[n][2]), f2tf(acc[n][3]));
        *reinterpret_cast<uint2*>(&As[(arow + g) * PAD + c]) = lo;
        *reinterpret_cast<uint2*>(&As[(arow + g + 8) * PAD + c]) = hi;
    }
    for (int i = tid; i < 64 * 16; i += 128) {
        int r = i >> 4;
        int c4 = (i & 15) << 2;
        float4 w = reinterpret_cast<const float4*>(W2)[i];
        uint4 tw;
        tw.x = f2tf(w.x); tw.y = f2tf(w.y); tw.z = f2tf(w.z); tw.w = f2tf(w.w);
        *reinterpret_cast<uint4*>(&Ws[r * PAD + c4]) = tw;
    }
    __syncthreads();

    // ---- GEMM 2: acc = T @ W2 ----
#pragma unroll
    for (int n = 0; n < 8; n++)
#pragma unroll
        for (int j = 0; j < 4; j++) acc[n][j] = 0.f;

#pragma unroll
    for (int k = 0; k < 8; k++) {
        uint32_t a0 = __float_as_uint(As[(arow + g) * PAD + k * 8 + th]);
        uint32_t a1 = __float_as_uint(As[(arow + g + 8) * PAD + k * 8 + th]);
        uint32_t a2 = __float_as_uint(As[(arow + g) * PAD + k * 8 + th + 4]);
        uint32_t a3 = __float_as_uint(As[(arow + g + 8) * PAD + k * 8 + th + 4]);
#pragma unroll
        for (int n = 0; n < 8; n++) {
            uint32_t bf0 = __float_as_uint(Ws[(k * 8 + th) * PAD + n * 8 + g]);
            uint32_t bf1 = __float_as_uint(Ws[(k * 8 + th + 4) * PAD + n * 8 + g]);
            mma_tf32(acc[n], a0, a1, a2, a3, bf0, bf1);
        }
    }

    // ---- bias + output ----
    int r0 = row0 + arow + g;
    int r1 = r0 + 8;
    bool v0 = (r0 < N_NODES);
    bool v1 = (r1 < N_NODES);

    if (mode == 0) {
#pragma unroll
        for (int n = 0; n < 8; n++) {
            int c = n * 8 + 2 * th;
            if (v0) {
                float2 o = make_float2(acc[n][0] + b2s[c], acc[n][1] + b2s[c + 1]);
                *reinterpret_cast<float2*>(&hout[(size_t)r0 * D + c]) = o;
            }
            if (v1) {
                float2 o = make_float2(acc[n][2] + b2s[c], acc[n][3] + b2s[c + 1]);
                *reinterpret_cast<float2*>(&hout[(size_t)r1 * D + c]) = o;
            }
        }
    } else {
        int gb0 = v0 ? batch[r0] : 0;
        int gb1 = v1 ? batch[r1] : 0;
        unsigned int* p0 = g_pool + (size_t)gb0 * D;
        unsigned int* p1 = g_pool + (size_t)gb1 * D;
#pragma unroll
        for (int n = 0; n < 8; n++) {
            int c = n * 8 + 2 * th;
#pragma unroll
            for (int j = 0; j < 4; j++) {
                float val = acc[n][j] + b2s[c + (j & 1)];
                unsigned int bits = __float_as_uint(val);
                unsigned int enc = (bits & 0x80000000u) ? ~bits : (bits | 0x80000000u);
                if (j < 2) { if (v0) atomicMax(&p0[c + (j & 1)], enc); }
                else       { if (v1) atomicMax(&p1[c + (j & 1)], enc); }
            }
        }
    }
}

// ---------------------------------------------------------------------------
__global__ void pool_init_kernel() {
    int i = blockIdx.x * blockDim.x + threadIdx.x;
    if (i < N_GRAPHS * D) g_pool[i] = 0x00800000u;  // encode(-FLT_MAX)
}

// ---------------------------------------------------------------------------
// FC head + log_softmax. One block (64 threads) per graph.
// ---------------------------------------------------------------------------
__global__ __launch_bounds__(64) void fc_kernel(const float* __restrict__ fcW1,
                                                const float* __restrict__ fcb1,
                                                const float* __restrict__ fcW2,
                                                const float* __restrict__ fcb2,
                                                float* __restrict__ out) {
    __shared__ float xr[D];
    __shared__ float hid[HID_FC];
    __shared__ float logits[N_CLASSES];
    __shared__ float m_s, lse_s;

    int g = blockIdx.x;
    int t = threadIdx.x;

    unsigned int e = g_pool[(size_t)g * D + t];
    unsigned int u = (e & 0x80000000u) ? (e & 0x7FFFFFFFu) : ~e;
    xr[t] = __uint_as_float(u);
    __syncthreads();

    float a = fcb1[t];
#pragma unroll
    for (int k = 0; k < D; k++) a += xr[k] * fcW1[k * HID_FC + t];
    hid[t] = fmaxf(a, 0.0f);
    __syncthreads();

    if (t < N_CLASSES) {
        float a2 = fcb2[t];
#pragma unroll
        for (int k = 0; k < HID_FC; k++) a2 += hid[k] * fcW2[k * N_CLASSES + t];
        logits[t] = a2;
    }
    __syncthreads();

    if (t == 0) {
        float m = logits[0];
#pragma unroll
        for (int j = 1; j < N_CLASSES; j++) m = fmaxf(m, logits[j]);
        float s = 0.0f;
#pragma unroll
        for (int j = 0; j < N_CLASSES; j++) s += expf(logits[j] - m);
        m_s = m;
        lse_s = logf(s);
    }
    __syncthreads();

    if (t < N_CLASSES) out[(size_t)g * N_CLASSES + t] = logits[t] - m_s - lse_s;
}

// ---------------------------------------------------------------------------
extern "C" void kernel_launch(void* const* d_in, const int* in_sizes, int n_in,
                              void* d_out, int out_size) {
    const float* x      = (const float*)d_in[0];
    const float* convW1 = (const float*)d_in[1];
    const float* convb1 = (const float*)d_in[2];
    const float* convW2 = (const float*)d_in[3];
    const float* convb2 = (const float*)d_in[4];
    const float* fcW1   = (const float*)d_in[5];
    const float* fcb1   = (const float*)d_in[6];
    const float* fcW2   = (const float*)d_in[7];
    const float* fcb2   = (const float*)d_in[8];
    const int* edge_index = (const int*)d_in[9];
    const int* batch      = (const int*)d_in[10];
    float* out = (float*)d_out;

    const int* src = edge_index;
    const int* dst = edge_index + N_EDGES;

    float* h_ptr = nullptr;
    float* agg_ptr = nullptr;
    int* deg_ptr = nullptr;
    cudaGetSymbolAddress((void**)&h_ptr, g_h);
    cudaGetSymbolAddress((void**)&agg_ptr, g_agg);
    cudaGetSymbolAddress((void**)&deg_ptr, g_deg);

    const int e4_blocks = (N_EDGES / 4 + 255) / 256;       // 782
    const int gather_blocks = (N_NODES * 16 + 255) / 256;  // 3125
    const int mlp_blocks = (N_NODES + 63) / 64;            // 782

    // ---- CSR build (per replay) ----
    cudaMemsetAsync(deg_ptr, 0, (size_t)N_NODES * sizeof(int));
    pool_init_kernel<<<(N_GRAPHS * D + 255) / 256, 256>>>();
    hist_kernel<<<e4_blocks, 256>>>(dst);
    scan_kernel<<<1, 1024>>>();
    fill_kernel<<<e4_blocks, 256>>>(src, dst);

    // ---- 3 GIN layers ----
    for (int l = 0; l < N_LAYERS; l++) {
        const float* hin = (l == 0) ? x : h_ptr;
        int mode = (l == N_LAYERS - 1) ? 1 : 0;
        gather_kernel<<<gather_blocks, 256>>>((const float4*)hin, (float4*)agg_ptr);
        mlp_tc_kernel<<<mlp_blocks, 128>>>(agg_ptr,
                                           convW1 + (size_t)l * D * D, convb1 + (size_t)l * D,
                                           convW2 + (size_t)l * D * D, convb2 + (size_t)l * D,
                                           h_ptr, batch, mode);
    }

    fc_kernel<<<N_GRAPHS, 64>>>(fcW1, fcb1, fcW2, fcb2, out);
}

// round 5
// speedup vs baseline: 1.8322x; 1.3536x over previous
#include <cuda_runtime.h>
#include <cstdint>

#define N_NODES 50000
#define N_EDGES 800000
#define D 64
#define N_GRAPHS 512
#define N_LAYERS 3
#define HID_FC 64
#define N_CLASSES 10
#define PAD 68    // smem row stride (floats)
#define CAP 128   // adjacency bucket capacity per node (mean deg = 16)

// Scratch (device globals: no allocations allowed)
__device__ float g_h[N_NODES * D];
__device__ float g_agg[N_NODES * D];
__device__ unsigned int g_pool[N_GRAPHS * D];
__device__ int g_cur[N_NODES];
__device__ int g_adj[N_NODES * CAP];
__device__ unsigned int g_w1t[N_LAYERS * D * D];  // tf32-converted weights
__device__ unsigned int g_w2t[N_LAYERS * D * D];

// ---------------------------------------------------------------------------
__device__ __forceinline__ uint32_t f2tf(float f) {
    uint32_t u;
    asm("cvt.rna.tf32.f32 %0, %1;" : "=r"(u) : "f"(f));
    return u;
}

// ---------------------------------------------------------------------------
// Weight pre-conversion to tf32 (once per replay; 3*2*4096 elems)
// ---------------------------------------------------------------------------
__global__ void prep_kernel(const float* __restrict__ convW1,
                            const float* __restrict__ convW2) {
    int i = blockIdx.x * blockDim.x + threadIdx.x;
    if (i < N_LAYERS * D * D) {
        g_w1t[i] = f2tf(convW1[i]);
        g_w2t[i] = f2tf(convW2[i]);
    }
}

// ---------------------------------------------------------------------------
// Bucket fill: g_adj[d*CAP + pos] = s for each edge (s -> d)
// ---------------------------------------------------------------------------
__global__ void fill_kernel(const int* __restrict__ src, const int* __restrict__ dst) {
    int e = (blockIdx.x * blockDim.x + threadIdx.x) * 4;
    if (e >= N_EDGES) return;  // N_EDGES % 4 == 0
    int4 d = *reinterpret_cast<const int4*>(dst + e);
    int4 s = *reinterpret_cast<const int4*>(src + e);
    int p0 = atomicAdd(&g_cur[d.x], 1);
    int p1 = atomicAdd(&g_cur[d.y], 1);
    int p2 = atomicAdd(&g_cur[d.z], 1);
    int p3 = atomicAdd(&g_cur[d.w], 1);
    g_adj[d.x * CAP + p0] = s.x;
    g_adj[d.y * CAP + p1] = s.y;
    g_adj[d.z * CAP + p2] = s.z;
    g_adj[d.w * CAP + p3] = s.w;
}

// ---------------------------------------------------------------------------
// Gather aggregation: agg[n] = h[n] + sum_{j in N(n)} h[j]
// 16 threads per node. Indices loaded coalesced (16/round) and shfl-broadcast;
// full rounds unroll 16 independent row loads into 4 accumulators.
// ---------------------------------------------------------------------------
__global__ __launch_bounds__(256) void gather_kernel(const float4* __restrict__ hin4,
                                                     float4* __restrict__ agg4) {
    unsigned int gid = blockIdx.x * 256u + threadIdx.x;
    unsigned int node = gid >> 4;
    unsigned int lane = gid & 15u;
    if (node >= N_NODES) return;
    unsigned int hm = 0xFFFFu << (threadIdx.x & 16);  // this 16-lane segment

    float4 a0 = hin4[(size_t)node * 16 + lane];  // self term (eps = 0)
    float4 a1 = make_float4(0.f, 0.f, 0.f, 0.f);
    float4 a2 = make_float4(0.f, 0.f, 0.f, 0.f);
    float4 a3 = make_float4(0.f, 0.f, 0.f, 0.f);

    int cnt = g_cur[node];
    const int* adj = g_adj + (size_t)node * CAP;

    for (int base = 0; base < cnt; base += 16) {
        int my = base + (int)lane;
        int idx = (my < cnt) ? adj[my] : 0;
        int m = cnt - base;
        if (m >= 16) {
#pragma unroll
            for (int j = 0; j < 16; j += 4) {
                int n0 = __shfl_sync(hm, idx, j + 0, 16);
                int n1 = __shfl_sync(hm, idx, j + 1, 16);
                int n2 = __shfl_sync(hm, idx, j + 2, 16);
                int n3 = __shfl_sync(hm, idx, j + 3, 16);
                float4 v0 = hin4[(size_t)n0 * 16 + lane];
                float4 v1 = hin4[(size_t)n1 * 16 + lane];
                float4 v2 = hin4[(size_t)n2 * 16 + lane];
                float4 v3 = hin4[(size_t)n3 * 16 + lane];
                a0.x += v0.x; a0.y += v0.y; a0.z += v0.z; a0.w += v0.w;
                a1.x += v1.x; a1.y += v1.y; a1.z += v1.z; a1.w += v1.w;
                a2.x += v2.x; a2.y += v2.y; a2.z += v2.z; a2.w += v2.w;
                a3.x += v3.x; a3.y += v3.y; a3.z += v3.z; a3.w += v3.w;
            }
        } else {
            for (int j = 0; j < m; j++) {
                int nb = __shfl_sync(hm, idx, j, 16);
                float4 v = hin4[(size_t)nb * 16 + lane];
                a0.x += v.x; a0.y += v.y; a0.z += v.z; a0.w += v.w;
            }
        }
    }
    a0.x += a1.x + a2.x + a3.x;
    a0.y += a1.y + a2.y + a3.y;
    a0.z += a1.z + a2.z + a3.z;
    a0.w += a1.w + a2.w + a3.w;

    agg4[(size_t)node * 16 + lane] = a0;
}

// ---------------------------------------------------------------------------
// TF32 tensor-core fused MLP: h_out = relu(agg @ W1 + b1) @ W2 + b2
// Block = 128 threads (4 warps) = 64-row tile. Weights pre-converted to tf32.
// mode 0: write hout; mode 1: fused global-max-pool into g_pool
// ---------------------------------------------------------------------------
__device__ __forceinline__ void mma_tf32(float* c, uint32_t a0, uint32_t a1,
                                         uint32_t a2, uint32_t a3,
                                         uint32_t b0, uint32_t b1) {
    asm volatile(
        "mma.sync.aligned.m16n8k8.row.col.f32.tf32.tf32.f32 "
        "{%0,%1,%2,%3}, {%4,%5,%6,%7}, {%8,%9}, {%0,%1,%2,%3};"
        : "+f"(c[0]), "+f"(c[1]), "+f"(c[2]), "+f"(c[3])
        : "r"(a0), "r"(a1), "r"(a2), "r"(a3), "r"(b0), "r"(b1));
}

__global__ __launch_bounds__(128) void mlp_tc_kernel(const float* __restrict__ xin,
                                                     const unsigned int* __restrict__ W1t,
                                                     const float* __restrict__ b1,
                                                     const unsigned int* __restrict__ W2t,
                                                     const float* __restrict__ b2,
                                                     float* __restrict__ hout,
                                                     const int* __restrict__ batch,
                                                     int mode) {
    __shared__ float As[64 * PAD];   // input tile, then T tile (tf32 bits)
    __shared__ float Ws[64 * PAD];   // W1, then W2 (tf32 bits)
    __shared__ float b1s[D];
    __shared__ float b2s[D];

    int tid = threadIdx.x;
    int warp = tid >> 5;
    int lane = tid & 31;
    int g = lane >> 2;   // group 0..7
    int th = lane & 3;   // thread-in-group 0..3
    int arow = warp * 16;
    int row0 = blockIdx.x * 64;

    // ---- stage A tile (cvt to tf32) + W1 (already tf32) ----
    for (int i = tid; i < 64 * 16; i += 128) {
        int r = i >> 4;
        int c4 = (i & 15) << 2;
        float4 v = make_float4(0.f, 0.f, 0.f, 0.f);
        if (row0 + r < N_NODES)
            v = reinterpret_cast<const float4*>(xin)[(size_t)(row0 + r) * 16 + (c4 >> 2)];
        uint4 t;
        t.x = f2tf(v.x); t.y = f2tf(v.y); t.z = f2tf(v.z); t.w = f2tf(v.w);
        *reinterpret_cast<uint4*>(&As[r * PAD + c4]) = t;

        uint4 tw = reinterpret_cast<const uint4*>(W1t)[i];
        *reinterpret_cast<uint4*>(&Ws[r * PAD + c4]) = tw;
    }
    if (tid < D) { b1s[tid] = b1[tid]; b2s[tid] = b2[tid]; }
    __syncthreads();

    // ---- GEMM 1: acc = A @ W1 ----
    float acc[8][4];
#pragma unroll
    for (int n = 0; n < 8; n++)
#pragma unroll
        for (int j = 0; j < 4; j++) acc[n][j] = 0.f;

#pragma unroll
    for (int k = 0; k < 8; k++) {
        uint32_t a0 = __float_as_uint(As[(arow + g) * PAD + k * 8 + th]);
        uint32_t a1 = __float_as_uint(As[(arow + g + 8) * PAD + k * 8 + th]);
        uint32_t a2 = __float_as_uint(As[(arow + g) * PAD + k * 8 + th + 4]);
        uint32_t a3 = __float_as_uint(As[(arow + g + 8) * PAD + k * 8 + th + 4]);
#pragma unroll
        for (int n = 0; n < 8; n++) {
            uint32_t bf0 = __float_as_uint(Ws[(k * 8 + th) * PAD + n * 8 + g]);
            uint32_t bf1 = __float_as_uint(Ws[(k * 8 + th + 4) * PAD + n * 8 + g]);
            mma_tf32(acc[n], a0, a1, a2, a3, bf0, bf1);
        }
    }

    // ---- bias + relu ----
#pragma unroll
    for (int n = 0; n < 8; n++) {
        int c = n * 8 + 2 * th;
        acc[n][0] = fmaxf(acc[n][0] + b1s[c], 0.f);
        acc[n][1] = fmaxf(acc[n][1] + b1s[c + 1], 0.f);
        acc[n][2] = fmaxf(acc[n][2] + b1s[c], 0.f);
        acc[n][3] = fmaxf(acc[n][3] + b1s[c + 1], 0.f);
    }

    __syncthreads();

    // ---- write T (tf32) into As; stage W2 ----
#pragma unroll
    for (int n = 0; n < 8; n++) {
        int c = n * 8 + 2 * th;
        uint2 lo = make_uint2(f2tf(acc[n][0]), f2tf(acc[n][1]));
        uint2 hi = make_uint2(f2tf(acc[n][2]), f2tf(acc[n][3]));
        *reinterpret_cast<uint2*>(&As[(arow + g) * PAD + c]) = lo;
        *reinterpret_cast<uint2*>(&As[(arow + g + 8) * PAD + c]) = hi;
    }
    for (int i = tid; i < 64 * 16; i += 128) {
        int r = i >> 4;
        int c4 = (i & 15) << 2;
        uint4 tw = reinterpret_cast<const uint4*>(W2t)[i];
        *reinterpret_cast<uint4*>(&Ws[r * PAD + c4]) = tw;
    }
    __syncthreads();

    // ---- GEMM 2: acc = T @ W2 ----
#pragma unroll
    for (int n = 0; n < 8; n++)
#pragma unroll
        for (int j = 0; j < 4; j++) acc[n][j] = 0.f;

#pragma unroll
    for (int k = 0; k < 8; k++) {
        uint32_t a0 = __float_as_uint(As[(arow + g) * PAD + k * 8 + th]);
        uint32_t a1 = __float_as_uint(As[(arow + g + 8) * PAD + k * 8 + th]);
        uint32_t a2 = __float_as_uint(As[(arow + g) * PAD + k * 8 + th + 4]);
        uint32_t a3 = __float_as_uint(As[(arow + g + 8) * PAD + k * 8 + th + 4]);
#pragma unroll
        for (int n = 0; n < 8; n++) {
            uint32_t bf0 = __float_as_uint(Ws[(k * 8 + th) * PAD + n * 8 + g]);
            uint32_t bf1 = __float_as_uint(Ws[(k * 8 + th + 4) * PAD + n * 8 + g]);
            mma_tf32(acc[n], a0, a1, a2, a3, bf0, bf1);
        }
    }

    // ---- bias + output ----
    int r0 = row0 + arow + g;
    int r1 = r0 + 8;
    bool v0 = (r0 < N_NODES);
    bool v1 = (r1 < N_NODES);

    if (mode == 0) {
#pragma unroll
        for (int n = 0; n < 8; n++) {
            int c = n * 8 + 2 * th;
            if (v0) {
                float2 o = make_float2(acc[n][0] + b2s[c], acc[n][1] + b2s[c + 1]);
                *reinterpret_cast<float2*>(&hout[(size_t)r0 * D + c]) = o;
            }
            if (v1) {
                float2 o = make_float2(acc[n][2] + b2s[c], acc[n][3] + b2s[c + 1]);
                *reinterpret_cast<float2*>(&hout[(size_t)r1 * D + c]) = o;
            }
        }
    } else {
        int gb0 = v0 ? batch[r0] : 0;
        int gb1 = v1 ? batch[r1] : 0;
        unsigned int* p0 = g_pool + (size_t)gb0 * D;
        unsigned int* p1 = g_pool + (size_t)gb1 * D;
#pragma unroll
        for (int n = 0; n < 8; n++) {
            int c = n * 8 + 2 * th;
#pragma unroll
            for (int j = 0; j < 4; j++) {
                float val = acc[n][j] + b2s[c + (j & 1)];
                unsigned int bits = __float_as_uint(val);
                unsigned int enc = (bits & 0x80000000u) ? ~bits : (bits | 0x80000000u);
                if (j < 2) { if (v0) atomicMax(&p0[c + (j & 1)], enc); }
                else       { if (v1) atomicMax(&p1[c + (j & 1)], enc); }
            }
        }
    }
}

// ---------------------------------------------------------------------------
__global__ void pool_init_kernel() {
    int i = blockIdx.x * blockDim.x + threadIdx.x;
    if (i < N_GRAPHS * D) g_pool[i] = 0x00800000u;  // encode(-FLT_MAX)
}

// ---------------------------------------------------------------------------
// FC head + log_softmax. One block (64 threads) per graph.
// ---------------------------------------------------------------------------
__global__ __launch_bounds__(64) void fc_kernel(const float* __restrict__ fcW1,
                                                const float* __restrict__ fcb1,
                                                const float* __restrict__ fcW2,
                                                const float* __restrict__ fcb2,
                                                float* __restrict__ out) {
    __shared__ float xr[D];
    __shared__ float hid[HID_FC];
    __shared__ float logits[N_CLASSES];
    __shared__ float m_s, lse_s;

    int g = blockIdx.x;
    int t = threadIdx.x;

    unsigned int e = g_pool[(size_t)g * D + t];
    unsigned int u = (e & 0x80000000u) ? (e & 0x7FFFFFFFu) : ~e;
    xr[t] = __uint_as_float(u);
    __syncthreads();

    float a = fcb1[t];
#pragma unroll
    for (int k = 0; k < D; k++) a += xr[k] * fcW1[k * HID_FC + t];
    hid[t] = fmaxf(a, 0.0f);
    __syncthreads();

    if (t < N_CLASSES) {
        float a2 = fcb2[t];
#pragma unroll
        for (int k = 0; k < HID_FC; k++) a2 += hid[k] * fcW2[k * N_CLASSES + t];
        logits[t] = a2;
    }
    __syncthreads();

    if (t == 0) {
        float m = logits[0];
#pragma unroll
        for (int j = 1; j < N_CLASSES; j++) m = fmaxf(m, logits[j]);
        float s = 0.0f;
#pragma unroll
        for (int j = 0; j < N_CLASSES; j++) s += expf(logits[j] - m);
        m_s = m;
        lse_s = logf(s);
    }
    __syncthreads();

    if (t < N_CLASSES) out[(size_t)g * N_CLASSES + t] = logits[t] - m_s - lse_s;
}

// ---------------------------------------------------------------------------
extern "C" void kernel_launch(void* const* d_in, const int* in_sizes, int n_in,
                              void* d_out, int out_size) {
    const float* x      = (const float*)d_in[0];
    const float* convW1 = (const float*)d_in[1];
    const float* convb1 = (const float*)d_in[2];
    const float* convW2 = (const float*)d_in[3];
    const float* convb2 = (const float*)d_in[4];
    const float* fcW1   = (const float*)d_in[5];
    const float* fcb1   = (const float*)d_in[6];
    const float* fcW2   = (const float*)d_in[7];
    const float* fcb2   = (const float*)d_in[8];
    const int* edge_index = (const int*)d_in[9];
    const int* batch      = (const int*)d_in[10];
    float* out = (float*)d_out;

    const int* src = edge_index;
    const int* dst = edge_index + N_EDGES;

    float* h_ptr = nullptr;
    float* agg_ptr = nullptr;
    int* cur_ptr = nullptr;
    unsigned int* w1t_ptr = nullptr;
    unsigned int* w2t_ptr = nullptr;
    cudaGetSymbolAddress((void**)&h_ptr, g_h);
    cudaGetSymbolAddress((void**)&agg_ptr, g_agg);
    cudaGetSymbolAddress((void**)&cur_ptr, g_cur);
    cudaGetSymbolAddress((void**)&w1t_ptr, g_w1t);
    cudaGetSymbolAddress((void**)&w2t_ptr, g_w2t);

    const int e4_blocks = (N_EDGES / 4 + 255) / 256;       // 782
    const int gather_blocks = (N_NODES * 16 + 255) / 256;  // 3125
    const int mlp_blocks = (N_NODES + 63) / 64;            // 782
    const int prep_blocks = (N_LAYERS * D * D + 255) / 256;

    // ---- per-replay setup ----
    cudaMemsetAsync(cur_ptr, 0, (size_t)N_NODES * sizeof(int));
    pool_init_kernel<<<(N_GRAPHS * D + 255) / 256, 256>>>();
    prep_kernel<<<prep_blocks, 256>>>(convW1, convW2);
    fill_kernel<<<e4_blocks, 256>>>(src, dst);

    // ---- 3 GIN layers ----
    for (int l = 0; l < N_LAYERS; l++) {
        const float* hin = (l == 0) ? x : h_ptr;
        int mode = (l == N_LAYERS - 1) ? 1 : 0;
        gather_kernel<<<gather_blocks, 256>>>((const float4*)hin, (float4*)agg_ptr);
        mlp_tc_kernel<<<mlp_blocks, 128>>>(agg_ptr,
                                           w1t_ptr + (size_t)l * D * D, convb1 + (size_t)l * D,
                                           w2t_ptr + (size_t)l * D * D, convb2 + (size_t)l * D,
                                           h_ptr, batch, mode);
    }

    fc_kernel<<<N_GRAPHS, 64>>>(fcW1, fcb1, fcW2, fcb2, out);
}

// round 6
// speedup vs baseline: 1.9839x; 1.0828x over previous
#include <cuda_runtime.h>
#include <cstdint>

#define N_NODES 50000
#define N_EDGES 800000
#define D 64
#define N_GRAPHS 512
#define N_LAYERS 3
#define HID_FC 64
#define N_CLASSES 10
#define PAD 68    // smem row stride (floats)
#define CAP 128   // adjacency bucket capacity per node (mean deg = 16)

// Scratch (device globals: no allocations allowed)
__device__ float g_h[N_NODES * D];
__device__ unsigned int g_aggt[N_NODES * D];      // tf32 bit patterns
__device__ unsigned int g_pool[N_GRAPHS * D];
__device__ int g_cur[N_NODES];
__device__ int g_adj[N_NODES * CAP];
__device__ unsigned int g_w1t[N_LAYERS * D * D];  // tf32-converted weights
__device__ unsigned int g_w2t[N_LAYERS * D * D];

// ---------------------------------------------------------------------------
__device__ __forceinline__ uint32_t f2tf(float f) {
    uint32_t u;
    asm("cvt.rna.tf32.f32 %0, %1;" : "=r"(u) : "f"(f));
    return u;
}

// ---------------------------------------------------------------------------
// Weight pre-conversion to tf32 + pool init (once per replay)
// ---------------------------------------------------------------------------
__global__ void prep_kernel(const float* __restrict__ convW1,
                            const float* __restrict__ convW2) {
    int i = blockIdx.x * blockDim.x + threadIdx.x;
    if (i < N_LAYERS * D * D) {
        g_w1t[i] = f2tf(convW1[i]);
        g_w2t[i] = f2tf(convW2[i]);
    }
    if (i < N_GRAPHS * D) g_pool[i] = 0x00800000u;  // encode(-FLT_MAX)
}

// ---------------------------------------------------------------------------
// Bucket fill: g_adj[d*CAP + pos] = s for each edge (s -> d). 8 edges/thread.
// ---------------------------------------------------------------------------
__global__ void fill_kernel(const int* __restrict__ src, const int* __restrict__ dst) {
    int e = (blockIdx.x * blockDim.x + threadIdx.x) * 8;
    if (e >= N_EDGES) return;  // N_EDGES % 8 == 0
    int4 d0 = *reinterpret_cast<const int4*>(dst + e);
    int4 d1 = *reinterpret_cast<const int4*>(dst + e + 4);
    int4 s0 = *reinterpret_cast<const int4*>(src + e);
    int4 s1 = *reinterpret_cast<const int4*>(src + e + 4);
    int p0 = atomicAdd(&g_cur[d0.x], 1);
    int p1 = atomicAdd(&g_cur[d0.y], 1);
    int p2 = atomicAdd(&g_cur[d0.z], 1);
    int p3 = atomicAdd(&g_cur[d0.w], 1);
    int p4 = atomicAdd(&g_cur[d1.x], 1);
    int p5 = atomicAdd(&g_cur[d1.y], 1);
    int p6 = atomicAdd(&g_cur[d1.z], 1);
    int p7 = atomicAdd(&g_cur[d1.w], 1);
    g_adj[d0.x * CAP + p0] = s0.x;
    g_adj[d0.y * CAP + p1] = s0.y;
    g_adj[d0.z * CAP + p2] = s0.z;
    g_adj[d0.w * CAP + p3] = s0.w;
    g_adj[d1.x * CAP + p4] = s1.x;
    g_adj[d1.y * CAP + p5] = s1.y;
    g_adj[d1.z * CAP + p6] = s1.z;
    g_adj[d1.w * CAP + p7] = s1.w;
}

// ---------------------------------------------------------------------------
// Gather aggregation: agg[n] = tf32(h[n] + sum_{j in N(n)} h[j])
// 16 threads per node; 2 accumulators + 4 independent load temps; occ-capped.
// ---------------------------------------------------------------------------
__global__ __launch_bounds__(256, 6) void gather_kernel(const float4* __restrict__ hin4,
                                                        uint4* __restrict__ aggt4) {
    unsigned int gid = blockIdx.x * 256u + threadIdx.x;
    unsigned int node = gid >> 4;
    unsigned int lane = gid & 15u;
    if (node >= N_NODES) return;
    unsigned int hm = 0xFFFFu << (threadIdx.x & 16);  // this 16-lane segment

    float4 a0 = hin4[(size_t)node * 16 + lane];  // self term (eps = 0)
    float4 a1 = make_float4(0.f, 0.f, 0.f, 0.f);

    int cnt = g_cur[node];
    const int* adj = g_adj + (size_t)node * CAP;

    for (int base = 0; base < cnt; base += 16) {
        int my = base + (int)lane;
        int idx = (my < cnt) ? __ldg(adj + my) : 0;
        int m = cnt - base;
        if (m >= 16) {
#pragma unroll
            for (int j = 0; j < 16; j += 4) {
                int n0 = __shfl_sync(hm, idx, j + 0, 16);
                int n1 = __shfl_sync(hm, idx, j + 1, 16);
                int n2 = __shfl_sync(hm, idx, j + 2, 16);
                int n3 = __shfl_sync(hm, idx, j + 3, 16);
                float4 v0 = hin4[(size_t)n0 * 16 + lane];
                float4 v1 = hin4[(size_t)n1 * 16 + lane];
                float4 v2 = hin4[(size_t)n2 * 16 + lane];
                float4 v3 = hin4[(size_t)n3 * 16 + lane];
                a0.x += v0.x; a0.y += v0.y; a0.z += v0.z; a0.w += v0.w;
                a1.x += v1.x; a1.y += v1.y; a1.z += v1.z; a1.w += v1.w;
                a0.x += v2.x; a0.y += v2.y; a0.z += v2.z; a0.w += v2.w;
                a1.x += v3.x; a1.y += v3.y; a1.z += v3.z; a1.w += v3.w;
            }
        } else {
            for (int j = 0; j < m; j++) {
                int nb = __shfl_sync(hm, idx, j, 16);
                float4 v = hin4[(size_t)nb * 16 + lane];
                a0.x += v.x; a0.y += v.y; a0.z += v.z; a0.w += v.w;
            }
        }
    }
    a0.x += a1.x; a0.y += a1.y; a0.z += a1.z; a0.w += a1.w;

    uint4 o;
    o.x = f2tf(a0.x); o.y = f2tf(a0.y); o.z = f2tf(a0.z); o.w = f2tf(a0.w);
    aggt4[(size_t)node * 16 + lane] = o;
}

// ---------------------------------------------------------------------------
// TF32 tensor-core fused MLP: h_out = relu(agg @ W1 + b1) @ W2 + b2
// Block = 128 threads (4 warps) = 64-row tile. A and W pre-converted to tf32.
// mode 0: write hout; mode 1: fused global-max-pool into g_pool
// ---------------------------------------------------------------------------
__device__ __forceinline__ void mma_tf32(float* c, uint32_t a0, uint32_t a1,
                                         uint32_t a2, uint32_t a3,
                                         uint32_t b0, uint32_t b1) {
    asm volatile(
        "mma.sync.aligned.m16n8k8.row.col.f32.tf32.tf32.f32 "
        "{%0,%1,%2,%3}, {%4,%5,%6,%7}, {%8,%9}, {%0,%1,%2,%3};"
        : "+f"(c[0]), "+f"(c[1]), "+f"(c[2]), "+f"(c[3])
        : "r"(a0), "r"(a1), "r"(a2), "r"(a3), "r"(b0), "r"(b1));
}

__global__ __launch_bounds__(128) void mlp_tc_kernel(const uint4* __restrict__ xint,
                                                     const unsigned int* __restrict__ W1t,
                                                     const float* __restrict__ b1,
                                                     const unsigned int* __restrict__ W2t,
                                                     const float* __restrict__ b2,
                                                     float* __restrict__ hout,
                                                     const int* __restrict__ batch,
                                                     int mode) {
    __shared__ float As[64 * PAD];   // input tile, then T tile (tf32 bits)
    __shared__ float Ws[64 * PAD];   // W1, then W2 (tf32 bits)
    __shared__ float b1s[D];
    __shared__ float b2s[D];

    int tid = threadIdx.x;
    int warp = tid >> 5;
    int lane = tid & 31;
    int g = lane >> 2;   // group 0..7
    int th = lane & 3;   // thread-in-group 0..3
    int arow = warp * 16;
    int row0 = blockIdx.x * 64;

    // ---- stage A tile (already tf32) + W1 (already tf32) ----
    for (int i = tid; i < 64 * 16; i += 128) {
        int r = i >> 4;
        int c4 = (i & 15) << 2;
        uint4 t = make_uint4(0u, 0u, 0u, 0u);
        if (row0 + r < N_NODES)
            t = xint[(size_t)(row0 + r) * 16 + (i & 15)];
        *reinterpret_cast<uint4*>(&As[r * PAD + c4]) = t;

        uint4 tw = reinterpret_cast<const uint4*>(W1t)[i];
        *reinterpret_cast<uint4*>(&Ws[r * PAD + c4]) = tw;
    }
    if (tid < D) { b1s[tid] = b1[tid]; b2s[tid] = b2[tid]; }
    __syncthreads();

    // ---- GEMM 1: acc = A @ W1 ----
    float acc[8][4];
#pragma unroll
    for (int n = 0; n < 8; n++)
#pragma unroll
        for (int j = 0; j < 4; j++) acc[n][j] = 0.f;

#pragma unroll
    for (int k = 0; k < 8; k++) {
        uint32_t a0 = __float_as_uint(As[(arow + g) * PAD + k * 8 + th]);
        uint32_t a1 = __float_as_uint(As[(arow + g + 8) * PAD + k * 8 + th]);
        uint32_t a2 = __float_as_uint(As[(arow + g) * PAD + k * 8 + th + 4]);
        uint32_t a3 = __float_as_uint(As[(arow + g + 8) * PAD + k * 8 + th + 4]);
#pragma unroll
        for (int n = 0; n < 8; n++) {
            uint32_t bf0 = __float_as_uint(Ws[(k * 8 + th) * PAD + n * 8 + g]);
            uint32_t bf1 = __float_as_uint(Ws[(k * 8 + th + 4) * PAD + n * 8 + g]);
            mma_tf32(acc[n], a0, a1, a2, a3, bf0, bf1);
        }
    }

    // ---- bias + relu ----
#pragma unroll
    for (int n = 0; n < 8; n++) {
        int c = n * 8 + 2 * th;
        acc[n][0] = fmaxf(acc[n][0] + b1s[c], 0.f);
        acc[n][1] = fmaxf(acc[n][1] + b1s[c + 1], 0.f);
        acc[n][2] = fmaxf(acc[n][2] + b1s[c], 0.f);
        acc[n][3] = fmaxf(acc[n][3] + b1s[c + 1], 0.f);
    }

    __syncthreads();

    // ---- write T (tf32) into As; stage W2 ----
#pragma unroll
    for (int n = 0; n < 8; n++) {
        int c = n * 8 + 2 * th;
        uint2 lo = make_uint2(f2tf(acc[n][0]), f2tf(acc[n][1]));
        uint2 hi = make_uint2(f2tf(acc[n][2]), f2tf(acc[n][3]));
        *reinterpret_cast<uint2*>(&As[(arow + g) * PAD + c]) = lo;
        *reinterpret_cast<uint2*>(&As[(arow + g + 8) * PAD + c]) = hi;
    }
    for (int i = tid; i < 64 * 16; i += 128) {
        int r = i >> 4;
        int c4 = (i & 15) << 2;
        uint4 tw = reinterpret_cast<const uint4*>(W2t)[i];
        *reinterpret_cast<uint4*>(&Ws[r * PAD + c4]) = tw;
    }
    __syncthreads();

    // ---- GEMM 2: acc = T @ W2 ----
#pragma unroll
    for (int n = 0; n < 8; n++)
#pragma unroll
        for (int j = 0; j < 4; j++) acc[n][j] = 0.f;

#pragma unroll
    for (int k = 0; k < 8; k++) {
        uint32_t a0 = __float_as_uint(As[(arow + g) * PAD + k * 8 + th]);
        uint32_t a1 = __float_as_uint(As[(arow + g + 8) * PAD + k * 8 + th]);
        uint32_t a2 = __float_as_uint(As[(arow + g) * PAD + k * 8 + th + 4]);
        uint32_t a3 = __float_as_uint(As[(arow + g + 8) * PAD + k * 8 + th + 4]);
#pragma unroll
        for (int n = 0; n < 8; n++) {
            uint32_t bf0 = __float_as_uint(Ws[(k * 8 + th) * PAD + n * 8 + g]);
            uint32_t bf1 = __float_as_uint(Ws[(k * 8 + th + 4) * PAD + n * 8 + g]);
            mma_tf32(acc[n], a0, a1, a2, a3, bf0, bf1);
        }
    }

    // ---- bias + output ----
    int r0 = row0 + arow + g;
    int r1 = r0 + 8;
    bool v0 = (r0 < N_NODES);
    bool v1 = (r1 < N_NODES);

    if (mode == 0) {
#pragma unroll
        for (int n = 0; n < 8; n++) {
            int c = n * 8 + 2 * th;
            if (v0) {
                float2 o = make_float2(acc[n][0] + b2s[c], acc[n][1] + b2s[c + 1]);
                *reinterpret_cast<float2*>(&hout[(size_t)r0 * D + c]) = o;
            }
            if (v1) {
                float2 o = make_float2(acc[n][2] + b2s[c], acc[n][3] + b2s[c + 1]);
                *reinterpret_cast<float2*>(&hout[(size_t)r1 * D + c]) = o;
            }
        }
    } else {
        int gb0 = v0 ? batch[r0] : 0;
        int gb1 = v1 ? batch[r1] : 0;
        unsigned int* p0 = g_pool + (size_t)gb0 * D;
        unsigned int* p1 = g_pool + (size_t)gb1 * D;
#pragma unroll
        for (int n = 0; n < 8; n++) {
            int c = n * 8 + 2 * th;
#pragma unroll
            for (int j = 0; j < 4; j++) {
                float val = acc[n][j] + b2s[c + (j & 1)];
                unsigned int bits = __float_as_uint(val);
                unsigned int enc = (bits & 0x80000000u) ? ~bits : (bits | 0x80000000u);
                if (j < 2) { if (v0) atomicMax(&p0[c + (j & 1)], enc); }
                else       { if (v1) atomicMax(&p1[c + (j & 1)], enc); }
            }
        }
    }
}

// ---------------------------------------------------------------------------
// FC head + log_softmax. One block (64 threads) per graph.
// ---------------------------------------------------------------------------
__global__ __launch_bounds__(64) void fc_kernel(const float* __restrict__ fcW1,
                                                const float* __restrict__ fcb1,
                                                const float* __restrict__ fcW2,
                                                const float* __restrict__ fcb2,
                                                float* __restrict__ out) {
    __shared__ float xr[D];
    __shared__ float hid[HID_FC];
    __shared__ float logits[N_CLASSES];
    __shared__ float m_s, lse_s;

    int g = blockIdx.x;
    int t = threadIdx.x;

    unsigned int e = g_pool[(size_t)g * D + t];
    unsigned int u = (e & 0x80000000u) ? (e & 0x7FFFFFFFu) : ~e;
    xr[t] = __uint_as_float(u);
    __syncthreads();

    float a = fcb1[t];
#pragma unroll
    for (int k = 0; k < D; k++) a += xr[k] * fcW1[k * HID_FC + t];
    hid[t] = fmaxf(a, 0.0f);
    __syncthreads();

    if (t < N_CLASSES) {
        float a2 = fcb2[t];
#pragma unroll
        for (int k = 0; k < HID_FC; k++) a2 += hid[k] * fcW2[k * N_CLASSES + t];
        logits[t] = a2;
    }
    __syncthreads();

    if (t == 0) {
        float m = logits[0];
#pragma unroll
        for (int j = 1; j < N_CLASSES; j++) m = fmaxf(m, logits[j]);
        float s = 0.0f;
#pragma unroll
        for (int j = 0; j < N_CLASSES; j++) s += expf(logits[j] - m);
        m_s = m;
        lse_s = logf(s);
    }
    __syncthreads();

    if (t < N_CLASSES) out[(size_t)g * N_CLASSES + t] = logits[t] - m_s - lse_s;
}

// ---------------------------------------------------------------------------
extern "C" void kernel_launch(void* const* d_in, const int* in_sizes, int n_in,
                              void* d_out, int out_size) {
    const float* x      = (const float*)d_in[0];
    const float* convW1 = (const float*)d_in[1];
    const float* convb1 = (const float*)d_in[2];
    const float* convW2 = (const float*)d_in[3];
    const float* convb2 = (const float*)d_in[4];
    const float* fcW1   = (const float*)d_in[5];
    const float* fcb1   = (const float*)d_in[6];
    const float* fcW2   = (const float*)d_in[7];
    const float* fcb2   = (const float*)d_in[8];
    const int* edge_index = (const int*)d_in[9];
    const int* batch      = (const int*)d_in[10];
    float* out = (float*)d_out;

    const int* src = edge_index;
    const int* dst = edge_index + N_EDGES;

    float* h_ptr = nullptr;
    unsigned int* aggt_ptr = nullptr;
    int* cur_ptr = nullptr;
    unsigned int* w1t_ptr = nullptr;
    unsigned int* w2t_ptr = nullptr;
    cudaGetSymbolAddress((void**)&h_ptr, g_h);
    cudaGetSymbolAddress((void**)&aggt_ptr, g_aggt);
    cudaGetSymbolAddress((void**)&cur_ptr, g_cur);
    cudaGetSymbolAddress((void**)&w1t_ptr, g_w1t);
    cudaGetSymbolAddress((void**)&w2t_ptr, g_w2t);

    const int e8_blocks = (N_EDGES / 8 + 255) / 256;       // 391
    const int gather_blocks = (N_NODES * 16 + 255) / 256;  // 3125
    const int mlp_blocks = (N_NODES + 63) / 64;            // 782
    const int prep_blocks = (N_GRAPHS * D + 255) / 256;    // covers both prep jobs

    // ---- per-replay setup ----
    cudaMemsetAsync(cur_ptr, 0, (size_t)N_NODES * sizeof(int));
    prep_kernel<<<prep_blocks, 256>>>(convW1, convW2);
    fill_kernel<<<e8_blocks, 256>>>(src, dst);

    // ---- 3 GIN layers ----
    for (int l = 0; l < N_LAYERS; l++) {
        const float* hin = (l == 0) ? x : h_ptr;
        int mode = (l == N_LAYERS - 1) ? 1 : 0;
        gather_kernel<<<gather_blocks, 256>>>((const float4*)hin, (uint4*)aggt_ptr);
        mlp_tc_kernel<<<mlp_blocks, 128>>>((const uint4*)aggt_ptr,
                                           w1t_ptr + (size_t)l * D * D, convb1 + (size_t)l * D,
                                           w2t_ptr + (size_t)l * D * D, convb2 + (size_t)l * D,
                                           h_ptr, batch, mode);
    }

    fc_kernel<<<N_GRAPHS, 64>>>(fcW1, fcb1, fcW2, fcb2, out);
}

// round 8
// speedup vs baseline: 2.0971x; 1.0570x over previous
#include <cuda_runtime.h>
#include <cstdint>

#define N_NODES 50000
#define N_EDGES 800000
#define D 64
#define N_GRAPHS 512
#define N_LAYERS 3
#define HID_FC 64
#define N_CLASSES 10
#define PAD_A 68   // smem row stride for A tiles: banks 4g+th -> conflict-free
#define PAD_B 72   // smem row stride for W tiles: banks 8th+g -> conflict-free
#define CAP 128    // adjacency bucket capacity per node (mean deg = 16)
#define MROWS 128  // rows per MLP block

// dynamic smem layout (floats): As[128*68] | Ws[64*72] | b1s[64] | b2s[64]
#define SMEM_FLOATS (MROWS * PAD_A + D * PAD_B + 2 * D)

// Scratch (device globals: no allocations allowed)
__device__ float g_h[N_NODES * D];
__device__ unsigned int g_aggt[N_NODES * D];      // tf32 bit patterns
__device__ unsigned int g_pool[N_GRAPHS * D];
__device__ int g_cur[N_NODES];
__device__ int g_adj[N_NODES * CAP];
__device__ unsigned int g_w1t[N_LAYERS * D * D];  // tf32-converted weights
__device__ unsigned int g_w2t[N_LAYERS * D * D];

// ---------------------------------------------------------------------------
__device__ __forceinline__ uint32_t f2tf(float f) {
    uint32_t u;
    asm("cvt.rna.tf32.f32 %0, %1;" : "=r"(u) : "f"(f));
    return u;
}

// ---------------------------------------------------------------------------
// Weight pre-conversion to tf32 + pool init (once per replay)
// ---------------------------------------------------------------------------
__global__ void prep_kernel(const float* __restrict__ convW1,
                            const float* __restrict__ convW2) {
    int i = blockIdx.x * blockDim.x + threadIdx.x;
    if (i < N_LAYERS * D * D) {
        g_w1t[i] = f2tf(convW1[i]);
        g_w2t[i] = f2tf(convW2[i]);
    }
    if (i < N_GRAPHS * D) g_pool[i] = 0x00800000u;  // encode(-FLT_MAX)
}

// ---------------------------------------------------------------------------
// Bucket fill: g_adj[d*CAP + pos] = s for each edge (s -> d). 8 edges/thread.
// ---------------------------------------------------------------------------
__global__ void fill_kernel(const int* __restrict__ src, const int* __restrict__ dst) {
    int e = (blockIdx.x * blockDim.x + threadIdx.x) * 8;
    if (e >= N_EDGES) return;  // N_EDGES % 8 == 0
    int4 d0 = *reinterpret_cast<const int4*>(dst + e);
    int4 d1 = *reinterpret_cast<const int4*>(dst + e + 4);
    int4 s0 = *reinterpret_cast<const int4*>(src + e);
    int4 s1 = *reinterpret_cast<const int4*>(src + e + 4);
    int p0 = atomicAdd(&g_cur[d0.x], 1);
    int p1 = atomicAdd(&g_cur[d0.y], 1);
    int p2 = atomicAdd(&g_cur[d0.z], 1);
    int p3 = atomicAdd(&g_cur[d0.w], 1);
    int p4 = atomicAdd(&g_cur[d1.x], 1);
    int p5 = atomicAdd(&g_cur[d1.y], 1);
    int p6 = atomicAdd(&g_cur[d1.z], 1);
    int p7 = atomicAdd(&g_cur[d1.w], 1);
    g_adj[d0.x * CAP + p0] = s0.x;
    g_adj[d0.y * CAP + p1] = s0.y;
    g_adj[d0.z * CAP + p2] = s0.z;
    g_adj[d0.w * CAP + p3] = s0.w;
    g_adj[d1.x * CAP + p4] = s1.x;
    g_adj[d1.y * CAP + p5] = s1.y;
    g_adj[d1.z * CAP + p6] = s1.z;
    g_adj[d1.w * CAP + p7] = s1.w;
}

// ---------------------------------------------------------------------------
// Gather aggregation: agg[n] = tf32(h[n] + sum_{j in N(n)} h[j])
// ---------------------------------------------------------------------------
__global__ __launch_bounds__(256, 6) void gather_kernel(const float4* __restrict__ hin4,
                                                        uint4* __restrict__ aggt4) {
    unsigned int gid = blockIdx.x * 256u + threadIdx.x;
    unsigned int node = gid >> 4;
    unsigned int lane = gid & 15u;
    if (node >= N_NODES) return;
    unsigned int hm = 0xFFFFu << (threadIdx.x & 16);  // this 16-lane segment

    float4 a0 = hin4[(size_t)node * 16 + lane];  // self term (eps = 0)
    float4 a1 = make_float4(0.f, 0.f, 0.f, 0.f);

    int cnt = g_cur[node];
    const int* adj = g_adj + (size_t)node * CAP;

    for (int base = 0; base < cnt; base += 16) {
        int my = base + (int)lane;
        int idx = (my < cnt) ? __ldg(adj + my) : 0;
        int m = cnt - base;
        if (m >= 16) {
#pragma unroll
            for (int j = 0; j < 16; j += 4) {
                int n0 = __shfl_sync(hm, idx, j + 0, 16);
                int n1 = __shfl_sync(hm, idx, j + 1, 16);
                int n2 = __shfl_sync(hm, idx, j + 2, 16);
                int n3 = __shfl_sync(hm, idx, j + 3, 16);
                float4 v0 = hin4[(size_t)n0 * 16 + lane];
                float4 v1 = hin4[(size_t)n1 * 16 + lane];
                float4 v2 = hin4[(size_t)n2 * 16 + lane];
                float4 v3 = hin4[(size_t)n3 * 16 + lane];
                a0.x += v0.x; a0.y += v0.y; a0.z += v0.z; a0.w += v0.w;
                a1.x += v1.x; a1.y += v1.y; a1.z += v1.z; a1.w += v1.w;
                a0.x += v2.x; a0.y += v2.y; a0.z += v2.z; a0.w += v2.w;
                a1.x += v3.x; a1.y += v3.y; a1.z += v3.z; a1.w += v3.w;
            }
        } else {
            for (int j = 0; j < m; j++) {
                int nb = __shfl_sync(hm, idx, j, 16);
                float4 v = hin4[(size_t)nb * 16 + lane];
                a0.x += v.x; a0.y += v.y; a0.z += v.z; a0.w += v.w;
            }
        }
    }
    a0.x += a1.x; a0.y += a1.y; a0.z += a1.z; a0.w += a1.w;

    uint4 o;
    o.x = f2tf(a0.x); o.y = f2tf(a0.y); o.z = f2tf(a0.z); o.w = f2tf(a0.w);
    aggt4[(size_t)node * 16 + lane] = o;
}

// ---------------------------------------------------------------------------
// TF32 tensor-core fused MLP: h_out = relu(agg @ W1 + b1) @ W2 + b2
// Block = 256 threads (8 warps) = 128-row tile; dynamic smem (53.8 KB).
// PAD_A/PAD_B split keeps both A and B fragment loads bank-conflict-free.
// mode 0: write hout; mode 1: fused global-max-pool into g_pool
// ---------------------------------------------------------------------------
__device__ __forceinline__ void mma_tf32(float* c, uint32_t a0, uint32_t a1,
                                         uint32_t a2, uint32_t a3,
                                         uint32_t b0, uint32_t b1) {
    asm volatile(
        "mma.sync.aligned.m16n8k8.row.col.f32.tf32.tf32.f32 "
        "{%0,%1,%2,%3}, {%4,%5,%6,%7}, {%8,%9}, {%0,%1,%2,%3};"
        : "+f"(c[0]), "+f"(c[1]), "+f"(c[2]), "+f"(c[3])
        : "r"(a0), "r"(a1), "r"(a2), "r"(a3), "r"(b0), "r"(b1));
}

__global__ __launch_bounds__(256) void mlp_tc_kernel(const uint4* __restrict__ xint,
                                                     const unsigned int* __restrict__ W1t,
                                                     const float* __restrict__ b1,
                                                     const unsigned int* __restrict__ W2t,
                                                     const float* __restrict__ b2,
                                                     float* __restrict__ hout,
                                                     const int* __restrict__ batch,
                                                     int mode) {
    extern __shared__ float smem[];
    float* As  = smem;                       // MROWS * PAD_A
    float* Ws  = As + MROWS * PAD_A;         // D * PAD_B
    float* b1s = Ws + D * PAD_B;             // D
    float* b2s = b1s + D;                    // D

    int tid = threadIdx.x;
    int warp = tid >> 5;
    int lane = tid & 31;
    int g = lane >> 2;   // group 0..7
    int th = lane & 3;   // thread-in-group 0..3
    int arow = warp * 16;
    int row0 = blockIdx.x * MROWS;

    // ---- stage A tile (already tf32) + W1 (already tf32) ----
    for (int i = tid; i < MROWS * 16; i += 256) {
        int r = i >> 4;
        uint4 t = make_uint4(0u, 0u, 0u, 0u);
        if (row0 + r < N_NODES)
            t = xint[(size_t)(row0 + r) * 16 + (i & 15)];
        *reinterpret_cast<uint4*>(&As[r * PAD_A + ((i & 15) << 2)]) = t;
    }
    for (int i = tid; i < D * 16; i += 256) {
        int r = i >> 4;
        uint4 tw = reinterpret_cast<const uint4*>(W1t)[i];
        *reinterpret_cast<uint4*>(&Ws[r * PAD_B + ((i & 15) << 2)]) = tw;
    }
    if (tid < D) { b1s[tid] = b1[tid]; b2s[tid] = b2[tid]; }
    __syncthreads();

    // ---- GEMM 1: acc = A @ W1 ----
    float acc[8][4];
#pragma unroll
    for (int n = 0; n < 8; n++)
#pragma unroll
        for (int j = 0; j < 4; j++) acc[n][j] = 0.f;

#pragma unroll
    for (int k = 0; k < 8; k++) {
        uint32_t a0 = __float_as_uint(As[(arow + g) * PAD_A + k * 8 + th]);
        uint32_t a1 = __float_as_uint(As[(arow + g + 8) * PAD_A + k * 8 + th]);
        uint32_t a2 = __float_as_uint(As[(arow + g) * PAD_A + k * 8 + th + 4]);
        uint32_t a3 = __float_as_uint(As[(arow + g + 8) * PAD_A + k * 8 + th + 4]);
#pragma unroll
        for (int n = 0; n < 8; n++) {
            uint32_t bf0 = __float_as_uint(Ws[(k * 8 + th) * PAD_B + n * 8 + g]);
            uint32_t bf1 = __float_as_uint(Ws[(k * 8 + th + 4) * PAD_B + n * 8 + g]);
            mma_tf32(acc[n], a0, a1, a2, a3, bf0, bf1);
        }
    }

    // ---- bias + relu ----
#pragma unroll
    for (int n = 0; n < 8; n++) {
        int c = n * 8 + 2 * th;
        acc[n][0] = fmaxf(acc[n][0] + b1s[c], 0.f);
        acc[n][1] = fmaxf(acc[n][1] + b1s[c + 1], 0.f);
        acc[n][2] = fmaxf(acc[n][2] + b1s[c], 0.f);
        acc[n][3] = fmaxf(acc[n][3] + b1s[c + 1], 0.f);
    }

    __syncthreads();

    // ---- write T (tf32) into As; stage W2 ----
#pragma unroll
    for (int n = 0; n < 8; n++) {
        int c = n * 8 + 2 * th;
        uint2 lo = make_uint2(f2tf(acc[n][0]), f2tf(acc[n][1]));
        uint2 hi = make_uint2(f2tf(acc[n][2]), f2tf(acc[n][3]));
        *reinterpret_cast<uint2*>(&As[(arow + g) * PAD_A + c]) = lo;
        *reinterpret_cast<uint2*>(&As[(arow + g + 8) * PAD_A + c]) = hi;
    }
    for (int i = tid; i < D * 16; i += 256) {
        int r = i >> 4;
        uint4 tw = reinterpret_cast<const uint4*>(W2t)[i];
        *reinterpret_cast<uint4*>(&Ws[r * PAD_B + ((i & 15) << 2)]) = tw;
    }
    __syncthreads();

    // ---- GEMM 2: acc = T @ W2 ----
#pragma unroll
    for (int n = 0; n < 8; n++)
#pragma unroll
        for (int j = 0; j < 4; j++) acc[n][j] = 0.f;

#pragma unroll
    for (int k = 0; k < 8; k++) {
        uint32_t a0 = __float_as_uint(As[(arow + g) * PAD_A + k * 8 + th]);
        uint32_t a1 = __float_as_uint(As[(arow + g + 8) * PAD_A + k * 8 + th]);
        uint32_t a2 = __float_as_uint(As[(arow + g) * PAD_A + k * 8 + th + 4]);
        uint32_t a3 = __float_as_uint(As[(arow + g + 8) * PAD_A + k * 8 + th + 4]);
#pragma unroll
        for (int n = 0; n < 8; n++) {
            uint32_t bf0 = __float_as_uint(Ws[(k * 8 + th) * PAD_B + n * 8 + g]);
            uint32_t bf1 = __float_as_uint(Ws[(k * 8 + th + 4) * PAD_B + n * 8 + g]);
            mma_tf32(acc[n], a0, a1, a2, a3, bf0, bf1);
        }
    }

    // ---- bias + output ----
    int r0 = row0 + arow + g;
    int r1 = r0 + 8;
    bool v0 = (r0 < N_NODES);
    bool v1 = (r1 < N_NODES);

    if (mode == 0) {
#pragma unroll
        for (int n = 0; n < 8; n++) {
            int c = n * 8 + 2 * th;
            if (v0) {
                float2 o = make_float2(acc[n][0] + b2s[c], acc[n][1] + b2s[c + 1]);
                *reinterpret_cast<float2*>(&hout[(size_t)r0 * D + c]) = o;
            }
            if (v1) {
                float2 o = make_float2(acc[n][2] + b2s[c], acc[n][3] + b2s[c + 1]);
                *reinterpret_cast<float2*>(&hout[(size_t)r1 * D + c]) = o;
            }
        }
    } else {
        int gb0 = v0 ? batch[r0] : 0;
        int gb1 = v1 ? batch[r1] : 0;
        unsigned int* p0 = g_pool + (size_t)gb0 * D;
        unsigned int* p1 = g_pool + (size_t)gb1 * D;
#pragma unroll
        for (int n = 0; n < 8; n++) {
            int c = n * 8 + 2 * th;
#pragma unroll
            for (int j = 0; j < 4; j++) {
                float val = acc[n][j] + b2s[c + (j & 1)];
                unsigned int bits = __float_as_uint(val);
                unsigned int enc = (bits & 0x80000000u) ? ~bits : (bits | 0x80000000u);
                if (j < 2) { if (v0) atomicMax(&p0[c + (j & 1)], enc); }
                else       { if (v1) atomicMax(&p1[c + (j & 1)], enc); }
            }
        }
    }
}

// ---------------------------------------------------------------------------
// FC head + log_softmax. One block (64 threads) per graph.
// ---------------------------------------------------------------------------
__global__ __launch_bounds__(64) void fc_kernel(const float* __restrict__ fcW1,
                                                const float* __restrict__ fcb1,
                                                const float* __restrict__ fcW2,
                                                const float* __restrict__ fcb2,
                                                float* __restrict__ out) {
    __shared__ float xr[D];
    __shared__ float hid[HID_FC];
    __shared__ float logits[N_CLASSES];
    __shared__ float m_s, lse_s;

    int g = blockIdx.x;
    int t = threadIdx.x;

    unsigned int e = g_pool[(size_t)g * D + t];
    unsigned int u = (e & 0x80000000u) ? (e & 0x7FFFFFFFu) : ~e;
    xr[t] = __uint_as_float(u);
    __syncthreads();

    float a = fcb1[t];
#pragma unroll
    for (int k = 0; k < D; k++) a += xr[k] * fcW1[k * HID_FC + t];
    hid[t] = fmaxf(a, 0.0f);
    __syncthreads();

    if (t < N_CLASSES) {
        float a2 = fcb2[t];
#pragma unroll
        for (int k = 0; k < HID_FC; k++) a2 += hid[k] * fcW2[k * N_CLASSES + t];
        logits[t] = a2;
    }
    __syncthreads();

    if (t == 0) {
        float m = logits[0];
#pragma unroll
        for (int j = 1; j < N_CLASSES; j++) m = fmaxf(m, logits[j]);
        float s = 0.0f;
#pragma unroll
        for (int j = 0; j < N_CLASSES; j++) s += expf(logits[j] - m);
        m_s = m;
        lse_s = logf(s);
    }
    __syncthreads();

    if (t < N_CLASSES) out[(size_t)g * N_CLASSES + t] = logits[t] - m_s - lse_s;
}

// ---------------------------------------------------------------------------
extern "C" void kernel_launch(void* const* d_in, const int* in_sizes, int n_in,
                              void* d_out, int out_size) {
    const float* x      = (const float*)d_in[0];
    const float* convW1 = (const float*)d_in[1];
    const float* convb1 = (const float*)d_in[2];
    const float* convW2 = (const float*)d_in[3];
    const float* convb2 = (const float*)d_in[4];
    const float* fcW1   = (const float*)d_in[5];
    const float* fcb1   = (const float*)d_in[6];
    const float* fcW2   = (const float*)d_in[7];
    const float* fcb2   = (const float*)d_in[8];
    const int* edge_index = (const int*)d_in[9];
    const int* batch      = (const int*)d_in[10];
    float* out = (float*)d_out;

    const int* src = edge_index;
    const int* dst = edge_index + N_EDGES;

    float* h_ptr = nullptr;
    unsigned int* aggt_ptr = nullptr;
    int* cur_ptr = nullptr;
    unsigned int* w1t_ptr = nullptr;
    unsigned int* w2t_ptr = nullptr;
    cudaGetSymbolAddress((void**)&h_ptr, g_h);
    cudaGetSymbolAddress((void**)&aggt_ptr, g_aggt);
    cudaGetSymbolAddress((void**)&cur_ptr, g_cur);
    cudaGetSymbolAddress((void**)&w1t_ptr, g_w1t);
    cudaGetSymbolAddress((void**)&w2t_ptr, g_w2t);

    const size_t mlp_smem = SMEM_FLOATS * sizeof(float);  // 53760 bytes
    cudaFuncSetAttribute(mlp_tc_kernel,
                         cudaFuncAttributeMaxDynamicSharedMemorySize,
                         (int)mlp_smem);

    const int e8_blocks = (N_EDGES / 8 + 255) / 256;         // 391
    const int gather_blocks = (N_NODES * 16 + 255) / 256;    // 3125
    const int mlp_blocks = (N_NODES + MROWS - 1) / MROWS;    // 391
    const int prep_blocks = (N_GRAPHS * D + 255) / 256;

    // ---- per-replay setup ----
    cudaMemsetAsync(cur_ptr, 0, (size_t)N_NODES * sizeof(int));
    prep_kernel<<<prep_blocks, 256>>>(convW1, convW2);
    fill_kernel<<<e8_blocks, 256>>>(src, dst);

    // ---- 3 GIN layers ----
    for (int l = 0; l < N_LAYERS; l++) {
        const float* hin = (l == 0) ? x : h_ptr;
        int mode = (l == N_LAYERS - 1) ? 1 : 0;
        gather_kernel<<<gather_blocks, 256>>>((const float4*)hin, (uint4*)aggt_ptr);
        mlp_tc_kernel<<<mlp_blocks, 256, mlp_smem>>>((const uint4*)aggt_ptr,
                                           w1t_ptr + (size_t)l * D * D, convb1 + (size_t)l * D,
                                           w2t_ptr + (size_t)l * D * D, convb2 + (size_t)l * D,
                                           h_ptr, batch, mode);
    }

    fc_kernel<<<N_GRAPHS, 64>>>(fcW1, fcb1, fcW2, fcb2, out);
}

// round 9
// speedup vs baseline: 2.1616x; 1.0308x over previous
#include <cuda_runtime.h>
#include <cstdint>

#define N_NODES 50000
#define N_EDGES 800000
#define D 64
#define N_GRAPHS 512
#define N_LAYERS 3
#define HID_FC 64
#define N_CLASSES 10
#define PAD_A 68   // smem row stride for A tiles: banks 4g+th -> conflict-free
#define PAD_B 72   // smem row stride for W tiles: banks 8th+g -> conflict-free
#define CAP 128    // adjacency bucket capacity per node (mean deg = 16)
#define MROWS 128  // rows per MLP block

// dynamic smem (floats): As[128*68] | Ws1[64*72] | Ws2[64*72] | b1s[64] | b2s[64]
#define SMEM_FLOATS (MROWS * PAD_A + 2 * D * PAD_B + 2 * D)

// Scratch (device globals: no allocations allowed)
__device__ float g_h[N_NODES * D];
__device__ unsigned int g_aggt[N_NODES * D];      // tf32 bit patterns
__device__ unsigned int g_pool[N_GRAPHS * D];
__device__ int g_cur[N_NODES];
__device__ int g_adj[N_NODES * CAP];
__device__ unsigned int g_w1t[N_LAYERS * D * D];  // tf32-converted weights
__device__ unsigned int g_w2t[N_LAYERS * D * D];

// ---------------------------------------------------------------------------
__device__ __forceinline__ uint32_t f2tf(float f) {
    uint32_t u;
    asm("cvt.rna.tf32.f32 %0, %1;" : "=r"(u) : "f"(f));
    return u;
}

// ---------------------------------------------------------------------------
// Weight pre-conversion to tf32 + pool init (once per replay)
// ---------------------------------------------------------------------------
__global__ void prep_kernel(const float* __restrict__ convW1,
                            const float* __restrict__ convW2) {
    int i = blockIdx.x * blockDim.x + threadIdx.x;
    if (i < N_LAYERS * D * D) {
        g_w1t[i] = f2tf(convW1[i]);
        g_w2t[i] = f2tf(convW2[i]);
    }
    if (i < N_GRAPHS * D) g_pool[i] = 0x00800000u;  // encode(-FLT_MAX)
}

// ---------------------------------------------------------------------------
// Bucket fill: g_adj[d*CAP + pos] = s for each edge (s -> d). 8 edges/thread.
// ---------------------------------------------------------------------------
__global__ void fill_kernel(const int* __restrict__ src, const int* __restrict__ dst) {
    int e = (blockIdx.x * blockDim.x + threadIdx.x) * 8;
    if (e >= N_EDGES) return;  // N_EDGES % 8 == 0
    int4 d0 = *reinterpret_cast<const int4*>(dst + e);
    int4 d1 = *reinterpret_cast<const int4*>(dst + e + 4);
    int4 s0 = *reinterpret_cast<const int4*>(src + e);
    int4 s1 = *reinterpret_cast<const int4*>(src + e + 4);
    int p0 = atomicAdd(&g_cur[d0.x], 1);
    int p1 = atomicAdd(&g_cur[d0.y], 1);
    int p2 = atomicAdd(&g_cur[d0.z], 1);
    int p3 = atomicAdd(&g_cur[d0.w], 1);
    int p4 = atomicAdd(&g_cur[d1.x], 1);
    int p5 = atomicAdd(&g_cur[d1.y], 1);
    int p6 = atomicAdd(&g_cur[d1.z], 1);
    int p7 = atomicAdd(&g_cur[d1.w], 1);
    g_adj[d0.x * CAP + p0] = s0.x;
    g_adj[d0.y * CAP + p1] = s0.y;
    g_adj[d0.z * CAP + p2] = s0.z;
    g_adj[d0.w * CAP + p3] = s0.w;
    g_adj[d1.x * CAP + p4] = s1.x;
    g_adj[d1.y * CAP + p5] = s1.y;
    g_adj[d1.z * CAP + p6] = s1.z;
    g_adj[d1.w * CAP + p7] = s1.w;
}

// ---------------------------------------------------------------------------
// Gather aggregation: agg[n] = tf32(h[n] + sum_{j in N(n)} h[j])
// ---------------------------------------------------------------------------
__global__ __launch_bounds__(256, 6) void gather_kernel(const float4* __restrict__ hin4,
                                                        uint4* __restrict__ aggt4) {
    unsigned int gid = blockIdx.x * 256u + threadIdx.x;
    unsigned int node = gid >> 4;
    unsigned int lane = gid & 15u;
    if (node >= N_NODES) return;
    unsigned int hm = 0xFFFFu << (threadIdx.x & 16);  // this 16-lane segment

    float4 a0 = hin4[(size_t)node * 16 + lane];  // self term (eps = 0)
    float4 a1 = make_float4(0.f, 0.f, 0.f, 0.f);

    int cnt = g_cur[node];
    const int* adj = g_adj + (size_t)node * CAP;

    for (int base = 0; base < cnt; base += 16) {
        int my = base + (int)lane;
        int idx = (my < cnt) ? __ldg(adj + my) : 0;
        int m = cnt - base;
        if (m >= 16) {
#pragma unroll
            for (int j = 0; j < 16; j += 4) {
                int n0 = __shfl_sync(hm, idx, j + 0, 16);
                int n1 = __shfl_sync(hm, idx, j + 1, 16);
                int n2 = __shfl_sync(hm, idx, j + 2, 16);
                int n3 = __shfl_sync(hm, idx, j + 3, 16);
                float4 v0 = hin4[(size_t)n0 * 16 + lane];
                float4 v1 = hin4[(size_t)n1 * 16 + lane];
                float4 v2 = hin4[(size_t)n2 * 16 + lane];
                float4 v3 = hin4[(size_t)n3 * 16 + lane];
                a0.x += v0.x; a0.y += v0.y; a0.z += v0.z; a0.w += v0.w;
                a1.x += v1.x; a1.y += v1.y; a1.z += v1.z; a1.w += v1.w;
                a0.x += v2.x; a0.y += v2.y; a0.z += v2.z; a0.w += v2.w;
                a1.x += v3.x; a1.y += v3.y; a1.z += v3.z; a1.w += v3.w;
            }
        } else {
            for (int j = 0; j < m; j++) {
                int nb = __shfl_sync(hm, idx, j, 16);
                float4 v = hin4[(size_t)nb * 16 + lane];
                a0.x += v.x; a0.y += v.y; a0.z += v.z; a0.w += v.w;
            }
        }
    }
    a0.x += a1.x; a0.y += a1.y; a0.z += a1.z; a0.w += a1.w;

    uint4 o;
    o.x = f2tf(a0.x); o.y = f2tf(a0.y); o.z = f2tf(a0.z); o.w = f2tf(a0.w);
    aggt4[(size_t)node * 16 + lane] = o;
}

// ---------------------------------------------------------------------------
// TF32 tensor-core fused MLP: h_out = relu(agg @ W1 + b1) @ W2 + b2
// Block = 256 threads (8 warps) = 128-row tile. ONE barrier: W1+W2 staged up
// front; GEMM2 A-fragments built from GEMM1 accumulators via shfl (C-frag and
// A-frag share 4-lane groups), so T never touches smem.
// mode 0: write hout; mode 1: fused global-max-pool into g_pool
// ---------------------------------------------------------------------------
__device__ __forceinline__ void mma_tf32(float* c, uint32_t a0, uint32_t a1,
                                         uint32_t a2, uint32_t a3,
                                         uint32_t b0, uint32_t b1) {
    asm volatile(
        "mma.sync.aligned.m16n8k8.row.col.f32.tf32.tf32.f32 "
        "{%0,%1,%2,%3}, {%4,%5,%6,%7}, {%8,%9}, {%0,%1,%2,%3};"
        : "+f"(c[0]), "+f"(c[1]), "+f"(c[2]), "+f"(c[3])
        : "r"(a0), "r"(a1), "r"(a2), "r"(a3), "r"(b0), "r"(b1));
}

__global__ __launch_bounds__(256, 3) void mlp_tc_kernel(const uint4* __restrict__ xint,
                                                        const unsigned int* __restrict__ W1t,
                                                        const float* __restrict__ b1,
                                                        const unsigned int* __restrict__ W2t,
                                                        const float* __restrict__ b2,
                                                        float* __restrict__ hout,
                                                        const int* __restrict__ batch,
                                                        int mode) {
    extern __shared__ float smem[];
    float* As  = smem;                        // MROWS * PAD_A
    float* Ws1 = As + MROWS * PAD_A;          // D * PAD_B
    float* Ws2 = Ws1 + D * PAD_B;             // D * PAD_B
    float* b1s = Ws2 + D * PAD_B;             // D
    float* b2s = b1s + D;                     // D

    int tid = threadIdx.x;
    int warp = tid >> 5;
    int lane = tid & 31;
    int g = lane >> 2;   // group 0..7
    int th = lane & 3;   // thread-in-group 0..3
    int arow = warp * 16;
    int row0 = blockIdx.x * MROWS;

    // ---- stage A tile + W1 + W2 (all tf32 already), single barrier ----
    for (int i = tid; i < MROWS * 16; i += 256) {
        int r = i >> 4;
        uint4 t = make_uint4(0u, 0u, 0u, 0u);
        if (row0 + r < N_NODES)
            t = xint[(size_t)(row0 + r) * 16 + (i & 15)];
        *reinterpret_cast<uint4*>(&As[r * PAD_A + ((i & 15) << 2)]) = t;
    }
    for (int i = tid; i < D * 16; i += 256) {
        int r = i >> 4;
        int c4 = (i & 15) << 2;
        uint4 t1 = reinterpret_cast<const uint4*>(W1t)[i];
        uint4 t2 = reinterpret_cast<const uint4*>(W2t)[i];
        *reinterpret_cast<uint4*>(&Ws1[r * PAD_B + c4]) = t1;
        *reinterpret_cast<uint4*>(&Ws2[r * PAD_B + c4]) = t2;
    }
    if (tid < D) { b1s[tid] = b1[tid]; b2s[tid] = b2[tid]; }
    __syncthreads();

    // ---- GEMM 1: acc = A @ W1 ----
    float acc[8][4];
#pragma unroll
    for (int n = 0; n < 8; n++)
#pragma unroll
        for (int j = 0; j < 4; j++) acc[n][j] = 0.f;

#pragma unroll
    for (int k = 0; k < 8; k++) {
        uint32_t a0 = __float_as_uint(As[(arow + g) * PAD_A + k * 8 + th]);
        uint32_t a1 = __float_as_uint(As[(arow + g + 8) * PAD_A + k * 8 + th]);
        uint32_t a2 = __float_as_uint(As[(arow + g) * PAD_A + k * 8 + th + 4]);
        uint32_t a3 = __float_as_uint(As[(arow + g + 8) * PAD_A + k * 8 + th + 4]);
#pragma unroll
        for (int n = 0; n < 8; n++) {
            uint32_t bf0 = __float_as_uint(Ws1[(k * 8 + th) * PAD_B + n * 8 + g]);
            uint32_t bf1 = __float_as_uint(Ws1[(k * 8 + th + 4) * PAD_B + n * 8 + g]);
            mma_tf32(acc[n], a0, a1, a2, a3, bf0, bf1);
        }
    }

    // ---- bias + relu (acc becomes T) ----
#pragma unroll
    for (int n = 0; n < 8; n++) {
        int c = n * 8 + 2 * th;
        acc[n][0] = fmaxf(acc[n][0] + b1s[c], 0.f);
        acc[n][1] = fmaxf(acc[n][1] + b1s[c + 1], 0.f);
        acc[n][2] = fmaxf(acc[n][2] + b1s[c], 0.f);
        acc[n][3] = fmaxf(acc[n][3] + b1s[c + 1], 0.f);
    }

    // ---- GEMM 2: acc2 = T @ W2; A-fragments from acc via intra-group shfl ----
    float acc2[8][4];
#pragma unroll
    for (int n = 0; n < 8; n++)
#pragma unroll
        for (int j = 0; j < 4; j++) acc2[n][j] = 0.f;

    int srcA = (lane & ~3) | (th >> 1);  // holds T cols k*8 + th
    int srcB = srcA + 2;                 // holds T cols k*8 + th + 4
    bool odd = (th & 1);

#pragma unroll
    for (int k = 0; k < 8; k++) {
        // T[g][k*8+th], T[g+8][k*8+th] from srcA; +4 columns from srcB.
        float t0A = __shfl_sync(0xffffffffu, acc[k][0], srcA);
        float t1A = __shfl_sync(0xffffffffu, acc[k][1], srcA);
        float t2A = __shfl_sync(0xffffffffu, acc[k][2], srcA);
        float t3A = __shfl_sync(0xffffffffu, acc[k][3], srcA);
        float t0B = __shfl_sync(0xffffffffu, acc[k][0], srcB);
        float t1B = __shfl_sync(0xffffffffu, acc[k][1], srcB);
        float t2B = __shfl_sync(0xffffffffu, acc[k][2], srcB);
        float t3B = __shfl_sync(0xffffffffu, acc[k][3], srcB);
        uint32_t a0 = f2tf(odd ? t1A : t0A);
        uint32_t a1 = f2tf(odd ? t3A : t2A);
        uint32_t a2 = f2tf(odd ? t1B : t0B);
        uint32_t a3 = f2tf(odd ? t3B : t2B);
#pragma unroll
        for (int n = 0; n < 8; n++) {
            uint32_t bf0 = __float_as_uint(Ws2[(k * 8 + th) * PAD_B + n * 8 + g]);
            uint32_t bf1 = __float_as_uint(Ws2[(k * 8 + th + 4) * PAD_B + n * 8 + g]);
            mma_tf32(acc2[n], a0, a1, a2, a3, bf0, bf1);
        }
    }

    // ---- bias + output ----
    int r0 = row0 + arow + g;
    int r1 = r0 + 8;
    bool v0 = (r0 < N_NODES);
    bool v1 = (r1 < N_NODES);

    if (mode == 0) {
#pragma unroll
        for (int n = 0; n < 8; n++) {
            int c = n * 8 + 2 * th;
            if (v0) {
                float2 o = make_float2(acc2[n][0] + b2s[c], acc2[n][1] + b2s[c + 1]);
                *reinterpret_cast<float2*>(&hout[(size_t)r0 * D + c]) = o;
            }
            if (v1) {
                float2 o = make_float2(acc2[n][2] + b2s[c], acc2[n][3] + b2s[c + 1]);
                *reinterpret_cast<float2*>(&hout[(size_t)r1 * D + c]) = o;
            }
        }
    } else {
        int gb0 = v0 ? batch[r0] : 0;
        int gb1 = v1 ? batch[r1] : 0;
        unsigned int* p0 = g_pool + (size_t)gb0 * D;
        unsigned int* p1 = g_pool + (size_t)gb1 * D;
#pragma unroll
        for (int n = 0; n < 8; n++) {
            int c = n * 8 + 2 * th;
#pragma unroll
            for (int j = 0; j < 4; j++) {
                float val = acc2[n][j] + b2s[c + (j & 1)];
                unsigned int bits = __float_as_uint(val);
                unsigned int enc = (bits & 0x80000000u) ? ~bits : (bits | 0x80000000u);
                if (j < 2) { if (v0) atomicMax(&p0[c + (j & 1)], enc); }
                else       { if (v1) atomicMax(&p1[c + (j & 1)], enc); }
            }
        }
    }
}

// ---------------------------------------------------------------------------
// FC head + log_softmax. One block (64 threads) per graph.
// ---------------------------------------------------------------------------
__global__ __launch_bounds__(64) void fc_kernel(const float* __restrict__ fcW1,
                                                const float* __restrict__ fcb1,
                                                const float* __restrict__ fcW2,
                                                const float* __restrict__ fcb2,
                                                float* __restrict__ out) {
    __shared__ float xr[D];
    __shared__ float hid[HID_FC];
    __shared__ float logits[N_CLASSES];
    __shared__ float m_s, lse_s;

    int g = blockIdx.x;
    int t = threadIdx.x;

    unsigned int e = g_pool[(size_t)g * D + t];
    unsigned int u = (e & 0x80000000u) ? (e & 0x7FFFFFFFu) : ~e;
    xr[t] = __uint_as_float(u);
    __syncthreads();

    float a = fcb1[t];
#pragma unroll
    for (int k = 0; k < D; k++) a += xr[k] * fcW1[k * HID_FC + t];
    hid[t] = fmaxf(a, 0.0f);
    __syncthreads();

    if (t < N_CLASSES) {
        float a2 = fcb2[t];
#pragma unroll
        for (int k = 0; k < HID_FC; k++) a2 += hid[k] * fcW2[k * N_CLASSES + t];
        logits[t] = a2;
    }
    __syncthreads();

    if (t == 0) {
        float m = logits[0];
#pragma unroll
        for (int j = 1; j < N_CLASSES; j++) m = fmaxf(m, logits[j]);
        float s = 0.0f;
#pragma unroll
        for (int j = 0; j < N_CLASSES; j++) s += expf(logits[j] - m);
        m_s = m;
        lse_s = logf(s);
    }
    __syncthreads();

    if (t < N_CLASSES) out[(size_t)g * N_CLASSES + t] = logits[t] - m_s - lse_s;
}

// ---------------------------------------------------------------------------
extern "C" void kernel_launch(void* const* d_in, const int* in_sizes, int n_in,
                              void* d_out, int out_size) {
    const float* x      = (const float*)d_in[0];
    const float* convW1 = (const float*)d_in[1];
    const float* convb1 = (const float*)d_in[2];
    const float* convW2 = (const float*)d_in[3];
    const float* convb2 = (const float*)d_in[4];
    const float* fcW1   = (const float*)d_in[5];
    const float* fcb1   = (const float*)d_in[6];
    const float* fcW2   = (const float*)d_in[7];
    const float* fcb2   = (const float*)d_in[8];
    const int* edge_index = (const int*)d_in[9];
    const int* batch      = (const int*)d_in[10];
    float* out = (float*)d_out;

    const int* src = edge_index;
    const int* dst = edge_index + N_EDGES;

    float* h_ptr = nullptr;
    unsigned int* aggt_ptr = nullptr;
    int* cur_ptr = nullptr;
    unsigned int* w1t_ptr = nullptr;
    unsigned int* w2t_ptr = nullptr;
    cudaGetSymbolAddress((void**)&h_ptr, g_h);
    cudaGetSymbolAddress((void**)&aggt_ptr, g_aggt);
    cudaGetSymbolAddress((void**)&cur_ptr, g_cur);
    cudaGetSymbolAddress((void**)&w1t_ptr, g_w1t);
    cudaGetSymbolAddress((void**)&w2t_ptr, g_w2t);

    const size_t mlp_smem = SMEM_FLOATS * sizeof(float);  // 72192 bytes
    cudaFuncSetAttribute(mlp_tc_kernel,
                         cudaFuncAttributeMaxDynamicSharedMemorySize,
                         (int)mlp_smem);

    const int e8_blocks = (N_EDGES / 8 + 255) / 256;         // 391
    const int gather_blocks = (N_NODES * 16 + 255) / 256;    // 3125
    const int mlp_blocks = (N_NODES + MROWS - 1) / MROWS;    // 391
    const int prep_blocks = (N_GRAPHS * D + 255) / 256;

    // ---- per-replay setup ----
    cudaMemsetAsync(cur_ptr, 0, (size_t)N_NODES * sizeof(int));
    prep_kernel<<<prep_blocks, 256>>>(convW1, convW2);
    fill_kernel<<<e8_blocks, 256>>>(src, dst);

    // ---- 3 GIN layers ----
    for (int l = 0; l < N_LAYERS; l++) {
        const float* hin = (l == 0) ? x : h_ptr;
        int mode = (l == N_LAYERS - 1) ? 1 : 0;
        gather_kernel<<<gather_blocks, 256>>>((const float4*)hin, (uint4*)aggt_ptr);
        mlp_tc_kernel<<<mlp_blocks, 256, mlp_smem>>>((const uint4*)aggt_ptr,
                                           w1t_ptr + (size_t)l * D * D, convb1 + (size_t)l * D,
                                           w2t_ptr + (size_t)l * D * D, convb2 + (size_t)l * D,
                                           h_ptr, batch, mode);
    }

    fc_kernel<<<N_GRAPHS, 64>>>(fcW1, fcb1, fcW2, fcb2, out);
}

// round 10
// speedup vs baseline: 2.1938x; 1.0149x over previous
#include <cuda_runtime.h>
#include <cuda_fp16.h>
#include <cstdint>

#define N_NODES 50000
#define N_EDGES 800000
#define D 64
#define N_GRAPHS 512
#define N_LAYERS 3
#define HID_FC 64
#define N_CLASSES 10
#define PAD_A 68   // smem row stride for A tiles: banks 4g+th -> conflict-free
#define PAD_B 72   // smem row stride for W tiles: banks 8th+g -> conflict-free
#define CAP 128    // adjacency bucket capacity per node (mean deg = 16)
#define MROWS 128  // rows per MLP block

// dynamic smem (floats): As[128*68] | Ws1[64*72] | Ws2[64*72] | b1s[64] | b2s[64]
#define SMEM_FLOATS (MROWS * PAD_A + 2 * D * PAD_B + 2 * D)

// Scratch (device globals: no allocations allowed)
__device__ __half g_h[N_NODES * D];               // layer activations, fp16
__device__ __half g_xh[N_NODES * D];              // input x converted to fp16
__device__ unsigned int g_aggt[N_NODES * D];      // tf32 bit patterns
__device__ unsigned int g_pool[N_GRAPHS * D];
__device__ int g_cur[N_NODES];
__device__ int g_adj[N_NODES * CAP];
__device__ unsigned int g_w1t[N_LAYERS * D * D];  // tf32-converted weights
__device__ unsigned int g_w2t[N_LAYERS * D * D];

// ---------------------------------------------------------------------------
__device__ __forceinline__ uint32_t f2tf(float f) {
    uint32_t u;
    asm("cvt.rna.tf32.f32 %0, %1;" : "=r"(u) : "f"(f));
    return u;
}

__device__ __forceinline__ float4 h4_to_f4(uint2 u) {
    float2 f0 = __half22float2(*reinterpret_cast<const __half2*>(&u.x));
    float2 f1 = __half22float2(*reinterpret_cast<const __half2*>(&u.y));
    return make_float4(f0.x, f0.y, f1.x, f1.y);
}

// ---------------------------------------------------------------------------
// Prep (once per replay): weights -> tf32, pool init, x -> fp16
// ---------------------------------------------------------------------------
__global__ void prep_kernel(const float* __restrict__ x,
                            const float* __restrict__ convW1,
                            const float* __restrict__ convW2) {
    int i = blockIdx.x * blockDim.x + threadIdx.x;
    if (i < N_LAYERS * D * D) {
        g_w1t[i] = f2tf(convW1[i]);
        g_w2t[i] = f2tf(convW2[i]);
    }
    if (i < N_GRAPHS * D) g_pool[i] = 0x00800000u;  // encode(-FLT_MAX)
    if (i < N_NODES * D / 2) {
        float2 v = reinterpret_cast<const float2*>(x)[i];
        reinterpret_cast<__half2*>(g_xh)[i] = __floats2half2_rn(v.x, v.y);
    }
}

// ---------------------------------------------------------------------------
// Bucket fill: g_adj[d*CAP + pos] = s for each edge (s -> d). 8 edges/thread.
// ---------------------------------------------------------------------------
__global__ void fill_kernel(const int* __restrict__ src, const int* __restrict__ dst) {
    int e = (blockIdx.x * blockDim.x + threadIdx.x) * 8;
    if (e >= N_EDGES) return;  // N_EDGES % 8 == 0
    int4 d0 = *reinterpret_cast<const int4*>(dst + e);
    int4 d1 = *reinterpret_cast<const int4*>(dst + e + 4);
    int4 s0 = *reinterpret_cast<const int4*>(src + e);
    int4 s1 = *reinterpret_cast<const int4*>(src + e + 4);
    int p0 = atomicAdd(&g_cur[d0.x], 1);
    int p1 = atomicAdd(&g_cur[d0.y], 1);
    int p2 = atomicAdd(&g_cur[d0.z], 1);
    int p3 = atomicAdd(&g_cur[d0.w], 1);
    int p4 = atomicAdd(&g_cur[d1.x], 1);
    int p5 = atomicAdd(&g_cur[d1.y], 1);
    int p6 = atomicAdd(&g_cur[d1.z], 1);
    int p7 = atomicAdd(&g_cur[d1.w], 1);
    g_adj[d0.x * CAP + p0] = s0.x;
    g_adj[d0.y * CAP + p1] = s0.y;
    g_adj[d0.z * CAP + p2] = s0.z;
    g_adj[d0.w * CAP + p3] = s0.w;
    g_adj[d1.x * CAP + p4] = s1.x;
    g_adj[d1.y * CAP + p5] = s1.y;
    g_adj[d1.z * CAP + p6] = s1.z;
    g_adj[d1.w * CAP + p7] = s1.w;
}

// ---------------------------------------------------------------------------
// Gather aggregation: agg[n] = tf32(h[n] + sum_{j in N(n)} h[j]); h is fp16.
// 16 threads per node, 4 halves (8B, uint2) per lane; fp32 accumulation.
// ---------------------------------------------------------------------------
__global__ __launch_bounds__(256, 6) void gather_kernel(const uint2* __restrict__ hin2,
                                                        uint4* __restrict__ aggt4) {
    unsigned int gid = blockIdx.x * 256u + threadIdx.x;
    unsigned int node = gid >> 4;
    unsigned int lane = gid & 15u;
    if (node >= N_NODES) return;
    unsigned int hm = 0xFFFFu << (threadIdx.x & 16);  // this 16-lane segment

    float4 a0 = h4_to_f4(hin2[(size_t)node * 16 + lane]);  // self term (eps = 0)
    float4 a1 = make_float4(0.f, 0.f, 0.f, 0.f);

    int cnt = g_cur[node];
    const int* adj = g_adj + (size_t)node * CAP;

    for (int base = 0; base < cnt; base += 16) {
        int my = base + (int)lane;
        int idx = (my < cnt) ? __ldg(adj + my) : 0;
        int m = cnt - base;
        if (m >= 16) {
#pragma unroll
            for (int j = 0; j < 16; j += 4) {
                int n0 = __shfl_sync(hm, idx, j + 0, 16);
                int n1 = __shfl_sync(hm, idx, j + 1, 16);
                int n2 = __shfl_sync(hm, idx, j + 2, 16);
                int n3 = __shfl_sync(hm, idx, j + 3, 16);
                float4 v0 = h4_to_f4(hin2[(size_t)n0 * 16 + lane]);
                float4 v1 = h4_to_f4(hin2[(size_t)n1 * 16 + lane]);
                float4 v2 = h4_to_f4(hin2[(size_t)n2 * 16 + lane]);
                float4 v3 = h4_to_f4(hin2[(size_t)n3 * 16 + lane]);
                a0.x += v0.x; a0.y += v0.y; a0.z += v0.z; a0.w += v0.w;
                a1.x += v1.x; a1.y += v1.y; a1.z += v1.z; a1.w += v1.w;
                a0.x += v2.x; a0.y += v2.y; a0.z += v2.z; a0.w += v2.w;
                a1.x += v3.x; a1.y += v3.y; a1.z += v3.z; a1.w += v3.w;
            }
        } else {
            for (int j = 0; j < m; j++) {
                int nb = __shfl_sync(hm, idx, j, 16);
                float4 v = h4_to_f4(hin2[(size_t)nb * 16 + lane]);
                a0.x += v.x; a0.y += v.y; a0.z += v.z; a0.w += v.w;
            }
        }
    }
    a0.x += a1.x; a0.y += a1.y; a0.z += a1.z; a0.w += a1.w;

    uint4 o;
    o.x = f2tf(a0.x); o.y = f2tf(a0.y); o.z = f2tf(a0.z); o.w = f2tf(a0.w);
    aggt4[(size_t)node * 16 + lane] = o;
}

// ---------------------------------------------------------------------------
// TF32 tensor-core fused MLP: h_out = relu(agg @ W1 + b1) @ W2 + b2
// Block = 256 threads (8 warps) = 128-row tile. ONE barrier; GEMM2 A-frags
// from GEMM1 accumulators via shfl. Output stored as fp16 (mode 0).
// mode 1: fused global-max-pool into g_pool
// ---------------------------------------------------------------------------
__device__ __forceinline__ void mma_tf32(float* c, uint32_t a0, uint32_t a1,
                                         uint32_t a2, uint32_t a3,
                                         uint32_t b0, uint32_t b1) {
    asm volatile(
        "mma.sync.aligned.m16n8k8.row.col.f32.tf32.tf32.f32 "
        "{%0,%1,%2,%3}, {%4,%5,%6,%7}, {%8,%9}, {%0,%1,%2,%3};"
        : "+f"(c[0]), "+f"(c[1]), "+f"(c[2]), "+f"(c[3])
        : "r"(a0), "r"(a1), "r"(a2), "r"(a3), "r"(b0), "r"(b1));
}

__global__ __launch_bounds__(256, 3) void mlp_tc_kernel(const uint4* __restrict__ xint,
                                                        const unsigned int* __restrict__ W1t,
                                                        const float* __restrict__ b1,
                                                        const unsigned int* __restrict__ W2t,
                                                        const float* __restrict__ b2,
                                                        __half* __restrict__ hout,
                                                        const int* __restrict__ batch,
                                                        int mode) {
    extern __shared__ float smem[];
    float* As  = smem;                        // MROWS * PAD_A
    float* Ws1 = As + MROWS * PAD_A;          // D * PAD_B
    float* Ws2 = Ws1 + D * PAD_B;             // D * PAD_B
    float* b1s = Ws2 + D * PAD_B;             // D
    float* b2s = b1s + D;                     // D

    int tid = threadIdx.x;
    int warp = tid >> 5;
    int lane = tid & 31;
    int g = lane >> 2;   // group 0..7
    int th = lane & 3;   // thread-in-group 0..3
    int arow = warp * 16;
    int row0 = blockIdx.x * MROWS;

    // ---- stage A tile + W1 + W2 (all tf32 already), single barrier ----
    for (int i = tid; i < MROWS * 16; i += 256) {
        int r = i >> 4;
        uint4 t = make_uint4(0u, 0u, 0u, 0u);
        if (row0 + r < N_NODES)
            t = xint[(size_t)(row0 + r) * 16 + (i & 15)];
        *reinterpret_cast<uint4*>(&As[r * PAD_A + ((i & 15) << 2)]) = t;
    }
    for (int i = tid; i < D * 16; i += 256) {
        int r = i >> 4;
        int c4 = (i & 15) << 2;
        uint4 t1 = reinterpret_cast<const uint4*>(W1t)[i];
        uint4 t2 = reinterpret_cast<const uint4*>(W2t)[i];
        *reinterpret_cast<uint4*>(&Ws1[r * PAD_B + c4]) = t1;
        *reinterpret_cast<uint4*>(&Ws2[r * PAD_B + c4]) = t2;
    }
    if (tid < D) { b1s[tid] = b1[tid]; b2s[tid] = b2[tid]; }
    __syncthreads();

    // ---- GEMM 1: acc = A @ W1 ----
    float acc[8][4];
#pragma unroll
    for (int n = 0; n < 8; n++)
#pragma unroll
        for (int j = 0; j < 4; j++) acc[n][j] = 0.f;

#pragma unroll
    for (int k = 0; k < 8; k++) {
        uint32_t a0 = __float_as_uint(As[(arow + g) * PAD_A + k * 8 + th]);
        uint32_t a1 = __float_as_uint(As[(arow + g + 8) * PAD_A + k * 8 + th]);
        uint32_t a2 = __float_as_uint(As[(arow + g) * PAD_A + k * 8 + th + 4]);
        uint32_t a3 = __float_as_uint(As[(arow + g + 8) * PAD_A + k * 8 + th + 4]);
#pragma unroll
        for (int n = 0; n < 8; n++) {
            uint32_t bf0 = __float_as_uint(Ws1[(k * 8 + th) * PAD_B + n * 8 + g]);
            uint32_t bf1 = __float_as_uint(Ws1[(k * 8 + th + 4) * PAD_B + n * 8 + g]);
            mma_tf32(acc[n], a0, a1, a2, a3, bf0, bf1);
        }
    }

    // ---- bias + relu (acc becomes T) ----
#pragma unroll
    for (int n = 0; n < 8; n++) {
        int c = n * 8 + 2 * th;
        acc[n][0] = fmaxf(acc[n][0] + b1s[c], 0.f);
        acc[n][1] = fmaxf(acc[n][1] + b1s[c + 1], 0.f);
        acc[n][2] = fmaxf(acc[n][2] + b1s[c], 0.f);
        acc[n][3] = fmaxf(acc[n][3] + b1s[c + 1], 0.f);
    }

    // ---- GEMM 2: acc2 = T @ W2; A-fragments from acc via intra-group shfl ----
    float acc2[8][4];
#pragma unroll
    for (int n = 0; n < 8; n++)
#pragma unroll
        for (int j = 0; j < 4; j++) acc2[n][j] = 0.f;

    int srcA = (lane & ~3) | (th >> 1);  // holds T cols k*8 + th
    int srcB = srcA + 2;                 // holds T cols k*8 + th + 4
    bool odd = (th & 1);

#pragma unroll
    for (int k = 0; k < 8; k++) {
        float t0A = __shfl_sync(0xffffffffu, acc[k][0], srcA);
        float t1A = __shfl_sync(0xffffffffu, acc[k][1], srcA);
        float t2A = __shfl_sync(0xffffffffu, acc[k][2], srcA);
        float t3A = __shfl_sync(0xffffffffu, acc[k][3], srcA);
        float t0B = __shfl_sync(0xffffffffu, acc[k][0], srcB);
        float t1B = __shfl_sync(0xffffffffu, acc[k][1], srcB);
        float t2B = __shfl_sync(0xffffffffu, acc[k][2], srcB);
        float t3B = __shfl_sync(0xffffffffu, acc[k][3], srcB);
        uint32_t a0 = f2tf(odd ? t1A : t0A);
        uint32_t a1 = f2tf(odd ? t3A : t2A);
        uint32_t a2 = f2tf(odd ? t1B : t0B);
        uint32_t a3 = f2tf(odd ? t3B : t2B);
#pragma unroll
        for (int n = 0; n < 8; n++) {
            uint32_t bf0 = __float_as_uint(Ws2[(k * 8 + th) * PAD_B + n * 8 + g]);
            uint32_t bf1 = __float_as_uint(Ws2[(k * 8 + th + 4) * PAD_B + n * 8 + g]);
            mma_tf32(acc2[n], a0, a1, a2, a3, bf0, bf1);
        }
    }

    // ---- bias + output ----
    int r0 = row0 + arow + g;
    int r1 = r0 + 8;
    bool v0 = (r0 < N_NODES);
    bool v1 = (r1 < N_NODES);

    if (mode == 0) {
#pragma unroll
        for (int n = 0; n < 8; n++) {
            int c = n * 8 + 2 * th;
            if (v0) {
                __half2 o = __floats2half2_rn(acc2[n][0] + b2s[c], acc2[n][1] + b2s[c + 1]);
                *reinterpret_cast<__half2*>(&hout[(size_t)r0 * D + c]) = o;
            }
            if (v1) {
                __half2 o = __floats2half2_rn(acc2[n][2] + b2s[c], acc2[n][3] + b2s[c + 1]);
                *reinterpret_cast<__half2*>(&hout[(size_t)r1 * D + c]) = o;
            }
        }
    } else {
        int gb0 = v0 ? batch[r0] : 0;
        int gb1 = v1 ? batch[r1] : 0;
        unsigned int* p0 = g_pool + (size_t)gb0 * D;
        unsigned int* p1 = g_pool + (size_t)gb1 * D;
#pragma unroll
        for (int n = 0; n < 8; n++) {
            int c = n * 8 + 2 * th;
#pragma unroll
            for (int j = 0; j < 4; j++) {
                float val = acc2[n][j] + b2s[c + (j & 1)];
                unsigned int bits = __float_as_uint(val);
                unsigned int enc = (bits & 0x80000000u) ? ~bits : (bits | 0x80000000u);
                if (j < 2) { if (v0) atomicMax(&p0[c + (j & 1)], enc); }
                else       { if (v1) atomicMax(&p1[c + (j & 1)], enc); }
            }
        }
    }
}

// ---------------------------------------------------------------------------
// FC head + log_softmax. One block (64 threads) per graph.
// ---------------------------------------------------------------------------
__global__ __launch_bounds__(64) void fc_kernel(const float* __restrict__ fcW1,
                                                const float* __restrict__ fcb1,
                                                const float* __restrict__ fcW2,
                                                const float* __restrict__ fcb2,
                                                float* __restrict__ out) {
    __shared__ float xr[D];
    __shared__ float hid[HID_FC];
    __shared__ float logits[N_CLASSES];
    __shared__ float m_s, lse_s;

    int g = blockIdx.x;
    int t = threadIdx.x;

    unsigned int e = g_pool[(size_t)g * D + t];
    unsigned int u = (e & 0x80000000u) ? (e & 0x7FFFFFFFu) : ~e;
    xr[t] = __uint_as_float(u);
    __syncthreads();

    float a = fcb1[t];
#pragma unroll
    for (int k = 0; k < D; k++) a += xr[k] * fcW1[k * HID_FC + t];
    hid[t] = fmaxf(a, 0.0f);
    __syncthreads();

    if (t < N_CLASSES) {
        float a2 = fcb2[t];
#pragma unroll
        for (int k = 0; k < HID_FC; k++) a2 += hid[k] * fcW2[k * N_CLASSES + t];
        logits[t] = a2;
    }
    __syncthreads();

    if (t == 0) {
        float m = logits[0];
#pragma unroll
        for (int j = 1; j < N_CLASSES; j++) m = fmaxf(m, logits[j]);
        float s = 0.0f;
#pragma unroll
        for (int j = 0; j < N_CLASSES; j++) s += expf(logits[j] - m);
        m_s = m;
        lse_s = logf(s);
    }
    __syncthreads();

    if (t < N_CLASSES) out[(size_t)g * N_CLASSES + t] = logits[t] - m_s - lse_s;
}

// ---------------------------------------------------------------------------
extern "C" void kernel_launch(void* const* d_in, const int* in_sizes, int n_in,
                              void* d_out, int out_size) {
    const float* x      = (const float*)d_in[0];
    const float* convW1 = (const float*)d_in[1];
    const float* convb1 = (const float*)d_in[2];
    const float* convW2 = (const float*)d_in[3];
    const float* convb2 = (const float*)d_in[4];
    const float* fcW1   = (const float*)d_in[5];
    const float* fcb1   = (const float*)d_in[6];
    const float* fcW2   = (const float*)d_in[7];
    const float* fcb2   = (const float*)d_in[8];
    const int* edge_index = (const int*)d_in[9];
    const int* batch      = (const int*)d_in[10];
    float* out = (float*)d_out;

    const int* src = edge_index;
    const int* dst = edge_index + N_EDGES;

    __half* h_ptr = nullptr;
    __half* xh_ptr = nullptr;
    unsigned int* aggt_ptr = nullptr;
    int* cur_ptr = nullptr;
    unsigned int* w1t_ptr = nullptr;
    unsigned int* w2t_ptr = nullptr;
    cudaGetSymbolAddress((void**)&h_ptr, g_h);
    cudaGetSymbolAddress((void**)&xh_ptr, g_xh);
    cudaGetSymbolAddress((void**)&aggt_ptr, g_aggt);
    cudaGetSymbolAddress((void**)&cur_ptr, g_cur);
    cudaGetSymbolAddress((void**)&w1t_ptr, g_w1t);
    cudaGetSymbolAddress((void**)&w2t_ptr, g_w2t);

    const size_t mlp_smem = SMEM_FLOATS * sizeof(float);  // 72192 bytes
    cudaFuncSetAttribute(mlp_tc_kernel,
                         cudaFuncAttributeMaxDynamicSharedMemorySize,
                         (int)mlp_smem);

    const int e8_blocks = (N_EDGES / 8 + 255) / 256;         // 391
    const int gather_blocks = (N_NODES * 16 + 255) / 256;    // 3125
    const int mlp_blocks = (N_NODES + MROWS - 1) / MROWS;    // 391
    const int prep_blocks = (N_NODES * D / 2 + 255) / 256;   // 6250 (covers all prep jobs)

    // ---- per-replay setup ----
    cudaMemsetAsync(cur_ptr, 0, (size_t)N_NODES * sizeof(int));
    prep_kernel<<<prep_blocks, 256>>>(x, convW1, convW2);
    fill_kernel<<<e8_blocks, 256>>>(src, dst);

    // ---- 3 GIN layers ----
    for (int l = 0; l < N_LAYERS; l++) {
        const __half* hin = (l == 0) ? xh_ptr : h_ptr;
        int mode = (l == N_LAYERS - 1) ? 1 : 0;
        gather_kernel<<<gather_blocks, 256>>>((const uint2*)hin, (uint4*)aggt_ptr);
        mlp_tc_kernel<<<mlp_blocks, 256, mlp_smem>>>((const uint4*)aggt_ptr,
                                           w1t_ptr + (size_t)l * D * D, convb1 + (size_t)l * D,
                                           w2t_ptr + (size_t)l * D * D, convb2 + (size_t)l * D,
                                           h_ptr, batch, mode);
    }

    fc_kernel<<<N_GRAPHS, 64>>>(fcW1, fcb1, fcW2, fcb2, out);
}